// round 10
// baseline (speedup 1.0000x reference)
#include <cuda_runtime.h>
#include <cuda_bf16.h>
#include <cstdint>
#include <math.h>

#define Bq   8
#define Lq   1024
#define Eq   512
#define Hq   8
#define HDq  64
#define Pq   2047
#define BLq  8192
#define QKVq 1536
#define SCALEF 0.044194173824159216f  // 1/sqrt(512)

__device__ float g_proj[(size_t)BLq * QKVq];
__device__ float g_pk[(size_t)(Pq + 1) * Eq];
__device__ float g_ctx[(size_t)BLq * Eq];
__device__ float g_attn_fb[(size_t)Bq * Hq * Lq * Lq];

#define OPSZ  (16*136)
#define SCORE_SMEM (128*260*4 + 4*OPSZ*4)       // 167936 bytes

__device__ __forceinline__ uint32_t f2tf32(float f) {
    uint32_t u;
    asm("cvt.rna.tf32.f32 %0, %1;" : "=r"(u) : "f"(f));
    return u;
}

__device__ __forceinline__ void mma_tf32(float c[4], const uint32_t a[4],
                                         const uint32_t b[2]) {
    asm volatile(
        "mma.sync.aligned.m16n8k8.row.col.f32.tf32.tf32.f32 "
        "{%0,%1,%2,%3}, {%4,%5,%6,%7}, {%8,%9}, {%0,%1,%2,%3};"
        : "+f"(c[0]), "+f"(c[1]), "+f"(c[2]), "+f"(c[3])
        : "r"(a[0]), "r"(a[1]), "r"(a[2]), "r"(a[3]), "r"(b[0]), "r"(b[1]));
}

// ---------------------------------------------------------------------------
// TF32 SGEMM, 2-stage pipelined: C[M,N] = A[M,K] @ W[N,K]^T (+bias).
// ---------------------------------------------------------------------------
__global__ void __launch_bounds__(256, 2)
gemm_tf32(const float* __restrict__ A, const float* __restrict__ W,
          const float* __restrict__ bias, float* __restrict__ C,
          int M, int N, int K, int lda, int ldw, int ldc)
{
    __shared__ uint32_t As[2][16][136];
    __shared__ uint32_t Bs[2][16][136];
    const int m0 = blockIdx.y * 128, n0 = blockIdx.x * 128;
    const int t = threadIdx.x, lane = t & 31, warp = t >> 5;
    const int wm = (warp & 1) * 64, wn = (warp >> 1) * 32;
    const int g = lane >> 2, q4 = lane & 3;
    const int r0 = t >> 2, kc = (t & 3) * 4;

    float acc[4][4][4] = {};
    float4 a0, a1, w0, w1;

    auto ldg = [&](int k0) {
        a0 = make_float4(0.f,0.f,0.f,0.f);
        a1 = make_float4(0.f,0.f,0.f,0.f);
        w0 = make_float4(0.f,0.f,0.f,0.f);
        w1 = make_float4(0.f,0.f,0.f,0.f);
        if (m0 + r0      < M) a0 = *(const float4*)(A + (size_t)(m0+r0)*lda + k0 + kc);
        if (m0 + r0 + 64 < M) a1 = *(const float4*)(A + (size_t)(m0+r0+64)*lda + k0 + kc);
        if (n0 + r0      < N) w0 = *(const float4*)(W + (size_t)(n0+r0)*ldw + k0 + kc);
        if (n0 + r0 + 64 < N) w1 = *(const float4*)(W + (size_t)(n0+r0+64)*ldw + k0 + kc);
    };
    auto sts = [&](int buf) {
        As[buf][kc][r0]      = f2tf32(a0.x); As[buf][kc+1][r0]      = f2tf32(a0.y);
        As[buf][kc+2][r0]    = f2tf32(a0.z); As[buf][kc+3][r0]      = f2tf32(a0.w);
        As[buf][kc][r0+64]   = f2tf32(a1.x); As[buf][kc+1][r0+64]   = f2tf32(a1.y);
        As[buf][kc+2][r0+64] = f2tf32(a1.z); As[buf][kc+3][r0+64]   = f2tf32(a1.w);
        Bs[buf][kc][r0]      = f2tf32(w0.x); Bs[buf][kc+1][r0]      = f2tf32(w0.y);
        Bs[buf][kc+2][r0]    = f2tf32(w0.z); Bs[buf][kc+3][r0]      = f2tf32(w0.w);
        Bs[buf][kc][r0+64]   = f2tf32(w1.x); Bs[buf][kc+1][r0+64]   = f2tf32(w1.y);
        Bs[buf][kc+2][r0+64] = f2tf32(w1.z); Bs[buf][kc+3][r0+64]   = f2tf32(w1.w);
    };

    const int nIt = K / 16;
    ldg(0); sts(0);
    __syncthreads();

    for (int it = 0; it < nIt; it++) {
        int buf = it & 1;
        if (it + 1 < nIt) ldg((it + 1) * 16);
        #pragma unroll
        for (int ks = 0; ks < 2; ks++) {
            const int kq = ks * 8;
            uint32_t af[4][4], bf[4][2];
            #pragma unroll
            for (int mi = 0; mi < 4; mi++) {
                int rm = wm + mi * 16;
                af[mi][0] = As[buf][kq + q4][rm + g];
                af[mi][1] = As[buf][kq + q4][rm + 8 + g];
                af[mi][2] = As[buf][kq + 4 + q4][rm + g];
                af[mi][3] = As[buf][kq + 4 + q4][rm + 8 + g];
            }
            #pragma unroll
            for (int ni = 0; ni < 4; ni++) {
                int cn = wn + ni * 8;
                bf[ni][0] = Bs[buf][kq + q4][cn + g];
                bf[ni][1] = Bs[buf][kq + 4 + q4][cn + g];
            }
            #pragma unroll
            for (int mi = 0; mi < 4; mi++)
                #pragma unroll
                for (int ni = 0; ni < 4; ni++)
                    mma_tf32(acc[mi][ni], af[mi], bf[ni]);
        }
        if (it + 1 < nIt) sts(buf ^ 1);
        __syncthreads();
    }

    #pragma unroll
    for (int mi = 0; mi < 4; mi++) {
        int row = m0 + wm + mi * 16 + g;
        #pragma unroll
        for (int ni = 0; ni < 4; ni++) {
            int col = n0 + wn + ni * 8 + 2 * q4;
            float b0 = bias ? bias[col] : 0.f, b1 = bias ? bias[col+1] : 0.f;
            if (row < M)
                *(float2*)(C + (size_t)row*ldc + col) =
                    make_float2(acc[mi][ni][0] + b0, acc[mi][ni][1] + b1);
            if (row + 8 < M)
                *(float2*)(C + (size_t)(row+8)*ldc + col) =
                    make_float2(acc[mi][ni][2] + b0, acc[mi][ni][3] + b1);
        }
    }
}

// ---------------------------------------------------------------------------
// TF32 fused score kernel (pipelined): logits = AC + shifted BD.
// ---------------------------------------------------------------------------
__global__ void __launch_bounds__(512)
score_tc(const float* __restrict__ ub, const float* __restrict__ vbb,
         float* __restrict__ attn)
{
    extern __shared__ char sm_raw[];
    float*    D  = (float*)sm_raw;                     // [128][260]
    uint32_t* OP = (uint32_t*)(sm_raw + 128*260*4);

    const int z = blockIdx.z, b = z >> 3, h = z & 7;
    const int q0 = blockIdx.y * 128, k0 = blockIdx.x * 128;
    const float* Aq = g_proj + (size_t)b*Lq*QKVq + h*192;
    const float* Bk = Aq + 64;
    const float* Pk = g_pk + h*64;
    float* Cc = attn + (size_t)z * Lq * Lq;
    const int j0 = k0 - q0 + 896;

    const int t = threadIdx.x, lane = t & 31, warp = t >> 5;
    const int wm = (warp & 3) * 32, wn = (warp >> 2) * 32;
    const int g = lane >> 2, q4 = lane & 3;
    const int lrow = t >> 2, lkc = (t & 3) * 4;

    float acc[2][4][4];
    float4 avr, bvr;

    auto Abuf = [&](int buf) { return OP + buf * 2 * OPSZ; };
    auto Bbuf = [&](int buf) { return OP + buf * 2 * OPSZ + OPSZ; };

    auto sts_a_bias = [&](int buf, const float* biasv, int d0) {
        const float* bp = biasv + h*64 + d0 + lkc;
        uint32_t* Ab = Abuf(buf);
        Ab[(lkc+0)*136 + lrow] = f2tf32((avr.x + bp[0]) * SCALEF);
        Ab[(lkc+1)*136 + lrow] = f2tf32((avr.y + bp[1]) * SCALEF);
        Ab[(lkc+2)*136 + lrow] = f2tf32((avr.z + bp[2]) * SCALEF);
        Ab[(lkc+3)*136 + lrow] = f2tf32((avr.w + bp[3]) * SCALEF);
    };
    auto sts_b = [&](int buf) {
        uint32_t* Bb = Bbuf(buf);
        Bb[(lkc+0)*136 + lrow] = f2tf32(bvr.x);
        Bb[(lkc+1)*136 + lrow] = f2tf32(bvr.y);
        Bb[(lkc+2)*136 + lrow] = f2tf32(bvr.z);
        Bb[(lkc+3)*136 + lrow] = f2tf32(bvr.w);
    };
    auto mma_step = [&](int buf) {
        const uint32_t* Ab = Abuf(buf);
        const uint32_t* Bb = Bbuf(buf);
        #pragma unroll
        for (int ks = 0; ks < 2; ks++) {
            const int kq = ks * 8;
            uint32_t af[2][4], bf[4][2];
            #pragma unroll
            for (int mi = 0; mi < 2; mi++) {
                int rm = wm + mi * 16;
                af[mi][0] = Ab[(kq + q4)*136 + rm + g];
                af[mi][1] = Ab[(kq + q4)*136 + rm + 8 + g];
                af[mi][2] = Ab[(kq + 4 + q4)*136 + rm + g];
                af[mi][3] = Ab[(kq + 4 + q4)*136 + rm + 8 + g];
            }
            #pragma unroll
            for (int ni = 0; ni < 4; ni++) {
                int cn = wn + ni * 8;
                bf[ni][0] = Bb[(kq + q4)*136 + cn + g];
                bf[ni][1] = Bb[(kq + 4 + q4)*136 + cn + g];
            }
            #pragma unroll
            for (int mi = 0; mi < 2; mi++)
                #pragma unroll
                for (int ni = 0; ni < 4; ni++)
                    mma_tf32(acc[mi][ni], af[mi], bf[ni]);
        }
    };
    auto zero_acc = [&]() {
        #pragma unroll
        for (int mi = 0; mi < 2; mi++)
            #pragma unroll
            for (int ni = 0; ni < 4; ni++)
                #pragma unroll
                for (int e = 0; e < 4; e++) acc[mi][ni][e] = 0.f;
    };

    #pragma unroll 1
    for (int jc = 0; jc < 2; jc++) {
        zero_acc();
        const float* Prow = Pk + (size_t)(j0 + jc*128 + lrow) * Eq;
        avr = *(const float4*)(Aq + (size_t)(q0+lrow)*QKVq + lkc);
        bvr = *(const float4*)(Prow + lkc);
        sts_a_bias(0, vbb, 0); sts_b(0);
        __syncthreads();
        #pragma unroll
        for (int it = 0; it < 4; it++) {
            int buf = it & 1;
            if (it < 3) {
                int d0 = (it + 1) * 16;
                avr = *(const float4*)(Aq + (size_t)(q0+lrow)*QKVq + d0 + lkc);
                bvr = *(const float4*)(Prow + d0 + lkc);
            }
            mma_step(buf);
            if (it < 3) { sts_a_bias(buf ^ 1, vbb, (it + 1) * 16); sts_b(buf ^ 1); }
            __syncthreads();
        }
        #pragma unroll
        for (int mi = 0; mi < 2; mi++) {
            int row = wm + mi * 16 + g;
            #pragma unroll
            for (int ni = 0; ni < 4; ni++) {
                int col = jc * 128 + wn + ni * 8 + 2 * q4;
                D[row*260 + col]         = acc[mi][ni][0];
                D[row*260 + col + 1]     = acc[mi][ni][1];
                D[(row+8)*260 + col]     = acc[mi][ni][2];
                D[(row+8)*260 + col + 1] = acc[mi][ni][3];
            }
        }
    }

    zero_acc();
    avr = *(const float4*)(Aq + (size_t)(q0+lrow)*QKVq + lkc);
    bvr = *(const float4*)(Bk + (size_t)(k0+lrow)*QKVq + lkc);
    __syncthreads();
    sts_a_bias(0, ub, 0); sts_b(0);
    __syncthreads();
    #pragma unroll
    for (int it = 0; it < 4; it++) {
        int buf = it & 1;
        if (it < 3) {
            int d0 = (it + 1) * 16;
            avr = *(const float4*)(Aq + (size_t)(q0+lrow)*QKVq + d0 + lkc);
            bvr = *(const float4*)(Bk + (size_t)(k0+lrow)*QKVq + d0 + lkc);
        }
        mma_step(buf);
        if (it < 3) { sts_a_bias(buf ^ 1, ub, (it + 1) * 16); sts_b(buf ^ 1); }
        __syncthreads();
    }

    #pragma unroll
    for (int mi = 0; mi < 2; mi++) {
        int row = wm + mi * 16 + g;
        #pragma unroll
        for (int ni = 0; ni < 4; ni++) {
            int c = wn + ni * 8 + 2 * q4;
            int jb = c - row + 127;
            *(float2*)(Cc + (size_t)(q0+row)*Lq + k0 + c) =
                make_float2(acc[mi][ni][0] + D[row*260 + jb],
                            acc[mi][ni][1] + D[row*260 + jb + 1]);
            int row2 = row + 8, jb2 = jb - 8;
            *(float2*)(Cc + (size_t)(q0+row2)*Lq + k0 + c) =
                make_float2(acc[mi][ni][2] + D[row2*260 + jb2],
                            acc[mi][ni][3] + D[row2*260 + jb2 + 1]);
        }
    }
}

// ---------------------------------------------------------------------------
// Fused softmax + ctx kernel. Per CTA: 128 q-rows, full k=1024.
//  P1: row max over logits.  P2: pipelined mma on unnormalized e=exp(v-max),
//  writing e to attn and accumulating row sums.  P3: scale acc by 1/sum,
//  store ctx, rescale attn rows in gmem.
// ---------------------------------------------------------------------------
__global__ void __launch_bounds__(256, 2)
ctx_sm(float* __restrict__ attn)
{
    const int z = blockIdx.z, b = z >> 3, h = z & 7;
    const int m0 = blockIdx.y * 128;
    float* Az = attn + (size_t)z * Lq * Lq + (size_t)m0 * Lq;   // this CTA's rows
    const float* Vm = g_proj + (size_t)b*Lq*QKVq + h*192 + 128;
    float*       Cm = g_ctx  + (size_t)b*Lq*Eq + h*64;

    __shared__ uint32_t As[2][16][136];
    __shared__ uint32_t Bs[2][16][72];
    __shared__ float Sm[128];
    __shared__ float Sinv[128];

    const int t = threadIdx.x, lane = t & 31, warp = t >> 5;
    const int wm = (warp & 3) * 32, wn = (warp >> 2) * 32;
    const int g = lane >> 2, q4 = lane & 3;
    const int r0 = t >> 2, kc = (t & 3) * 4;   // A loader: rows r0, r0+64
    const int br = t >> 4, bc = (t & 15) * 4;  // B loader

    // ---- P1: row max ----
    {
        int row = t >> 1, half = t & 1;
        const float4* rp = (const float4*)(Az + (size_t)row * Lq + half * 512);
        float m = -1e30f;
        #pragma unroll 4
        for (int i = 0; i < 128; i++) {
            float4 v = rp[i];
            m = fmaxf(m, fmaxf(fmaxf(v.x, v.y), fmaxf(v.z, v.w)));
        }
        m = fmaxf(m, __shfl_xor_sync(0xffffffffu, m, 1));
        if (half == 0) Sm[row] = m;
    }
    __syncthreads();

    const float mR0 = Sm[r0], mR1 = Sm[r0 + 64];
    float psum0 = 0.f, psum1 = 0.f;

    float acc[2][4][4] = {};
    float4 a0r, a1r, bvr;

    auto ldg = [&](int k0) {
        a0r = *(const float4*)(Az + (size_t)r0 * Lq + k0 + kc);
        a1r = *(const float4*)(Az + (size_t)(r0+64) * Lq + k0 + kc);
        bvr = *(const float4*)(Vm + (size_t)(k0+br)*QKVq + bc);
    };
    auto sts = [&](int buf, int k0) {
        float4 e0, e1;
        e0.x = expf(a0r.x - mR0); e0.y = expf(a0r.y - mR0);
        e0.z = expf(a0r.z - mR0); e0.w = expf(a0r.w - mR0);
        e1.x = expf(a1r.x - mR1); e1.y = expf(a1r.y - mR1);
        e1.z = expf(a1r.z - mR1); e1.w = expf(a1r.w - mR1);
        psum0 += (e0.x + e0.y) + (e0.z + e0.w);
        psum1 += (e1.x + e1.y) + (e1.z + e1.w);
        *(float4*)(Az + (size_t)r0 * Lq + k0 + kc)      = e0;
        *(float4*)(Az + (size_t)(r0+64) * Lq + k0 + kc) = e1;
        As[buf][kc][r0]      = f2tf32(e0.x); As[buf][kc+1][r0]      = f2tf32(e0.y);
        As[buf][kc+2][r0]    = f2tf32(e0.z); As[buf][kc+3][r0]      = f2tf32(e0.w);
        As[buf][kc][r0+64]   = f2tf32(e1.x); As[buf][kc+1][r0+64]   = f2tf32(e1.y);
        As[buf][kc+2][r0+64] = f2tf32(e1.z); As[buf][kc+3][r0+64]   = f2tf32(e1.w);
        Bs[buf][br][bc]   = f2tf32(bvr.x); Bs[buf][br][bc+1] = f2tf32(bvr.y);
        Bs[buf][br][bc+2] = f2tf32(bvr.z); Bs[buf][br][bc+3] = f2tf32(bvr.w);
    };

    ldg(0); sts(0, 0);
    __syncthreads();

    for (int it = 0; it < 64; it++) {
        int buf = it & 1;
        if (it + 1 < 64) ldg((it + 1) * 16);
        #pragma unroll
        for (int ks = 0; ks < 2; ks++) {
            const int kq = ks * 8;
            uint32_t af[2][4], bf[4][2];
            #pragma unroll
            for (int mi = 0; mi < 2; mi++) {
                int rm = wm + mi * 16;
                af[mi][0] = As[buf][kq + q4][rm + g];
                af[mi][1] = As[buf][kq + q4][rm + 8 + g];
                af[mi][2] = As[buf][kq + 4 + q4][rm + g];
                af[mi][3] = As[buf][kq + 4 + q4][rm + 8 + g];
            }
            #pragma unroll
            for (int ni = 0; ni < 4; ni++) {
                int cn = wn + ni * 8;
                bf[ni][0] = Bs[buf][kq + q4][cn + g];
                bf[ni][1] = Bs[buf][kq + 4 + q4][cn + g];
            }
            #pragma unroll
            for (int mi = 0; mi < 2; mi++)
                #pragma unroll
                for (int ni = 0; ni < 4; ni++)
                    mma_tf32(acc[mi][ni], af[mi], bf[ni]);
        }
        if (it + 1 < 64) sts(buf ^ 1, (it + 1) * 16);
        __syncthreads();
    }

    // ---- reduce row sums (4 consecutive threads own one row's columns) ----
    psum0 += __shfl_xor_sync(0xffffffffu, psum0, 1);
    psum0 += __shfl_xor_sync(0xffffffffu, psum0, 2);
    psum1 += __shfl_xor_sync(0xffffffffu, psum1, 1);
    psum1 += __shfl_xor_sync(0xffffffffu, psum1, 2);
    if ((t & 3) == 0) {
        Sinv[r0]      = 1.0f / psum0;
        Sinv[r0 + 64] = 1.0f / psum1;
    }
    __syncthreads();

    // ---- store ctx scaled by 1/sum ----
    #pragma unroll
    for (int mi = 0; mi < 2; mi++) {
        int row = wm + mi * 16 + g;
        float i0 = Sinv[row], i1 = Sinv[row + 8];
        #pragma unroll
        for (int ni = 0; ni < 4; ni++) {
            int col = wn + ni * 8 + 2 * q4;
            *(float2*)(Cm + (size_t)(m0+row)*Eq + col) =
                make_float2(acc[mi][ni][0] * i0, acc[mi][ni][1] * i0);
            *(float2*)(Cm + (size_t)(m0+row+8)*Eq + col) =
                make_float2(acc[mi][ni][2] * i1, acc[mi][ni][3] * i1);
        }
    }

    // ---- P3: rescale attn rows in gmem (normalize) ----
    for (int i = t; i < 128 * 256; i += 256) {
        int row = i >> 8, c = i & 255;
        float inv = Sinv[row];
        float4* p = (float4*)(Az + (size_t)row * Lq) + c;
        float4 v = *p;
        v.x *= inv; v.y *= inv; v.z *= inv; v.w *= inv;
        *p = v;
    }
}

// ---------------------------------------------------------------------------
extern "C" void kernel_launch(void* const* d_in, const int* in_sizes, int n_in,
                              void* d_out, int out_size)
{
    const float* x     = (const float*)d_in[0];
    const float* pos   = (const float*)d_in[1];
    const float* w_in  = (const float*)d_in[2];
    const float* w_pos = (const float*)d_in[3];
    const float* w_out = (const float*)d_in[4];
    const float* b_out = (const float*)d_in[5];
    const float* ub    = (const float*)d_in[6];
    const float* vbb   = (const float*)d_in[7];
    float* out = (float*)d_out;

    float *proj, *pk, *ctx, *attn_fb;
    cudaGetSymbolAddress((void**)&proj,    g_proj);
    cudaGetSymbolAddress((void**)&pk,      g_pk);
    cudaGetSymbolAddress((void**)&ctx,     g_ctx);
    cudaGetSymbolAddress((void**)&attn_fb, g_attn_fb);

    cudaFuncSetAttribute(score_tc, cudaFuncAttributeMaxDynamicSharedMemorySize,
                         SCORE_SMEM);

    const size_t OUT_E  = (size_t)BLq * Eq;
    const size_t ATTN_E = (size_t)Bq * Hq * Lq * Lq;
    float* attn = ((size_t)out_size >= OUT_E + ATTN_E) ? (out + OUT_E) : attn_fb;

    // 1) QKV projection - TF32
    gemm_tf32<<<dim3(QKVq/128, BLq/128), 256>>>(x, w_in, nullptr, proj,
                                                BLq, QKVq, Eq, Eq, Eq, QKVq);
    // 2) positional keys - TF32
    gemm_tf32<<<dim3(Eq/128, (Pq+127)/128), 256>>>(pos, w_pos, nullptr, pk,
                                                   Pq, Eq, Eq, Eq, Eq, Eq);
    // 3) fused AC + shifted BD logits - TF32
    score_tc<<<dim3(Lq/128, Lq/128, Bq*Hq), 512, SCORE_SMEM>>>(ub, vbb, attn);
    // 4+5) fused softmax + ctx = attn @ V
    ctx_sm<<<dim3(1, Lq/128, Bq*Hq), 256>>>(attn);
    // 6) out projection + bias - TF32
    gemm_tf32<<<dim3(Eq/128, BLq/128), 256>>>(ctx, w_out, b_out, out,
                                              BLq, Eq, Eq, Eq, Eq, Eq);
}

// round 11
// speedup vs baseline: 1.2271x; 1.2271x over previous
#include <cuda_runtime.h>
#include <cuda_bf16.h>
#include <cuda_fp16.h>
#include <cstdint>
#include <math.h>

#define Bq   8
#define Lq   1024
#define Eq   512
#define Hq   8
#define HDq  64
#define Pq   2047
#define BLq  8192
#define QKVq 1536
#define SCALEF 0.044194173824159216f  // 1/sqrt(512)

__device__ float g_proj[(size_t)BLq * QKVq];
__device__ float g_pk[(size_t)(Pq + 1) * Eq];   // +1 pad row (zero)
__device__ float g_ctx[(size_t)BLq * Eq];
__device__ float g_attn_fb[(size_t)Bq * Hq * Lq * Lq];

// score smem: Q[128][68] + K[128][68] + P[256][68] (fp32) + D[128][260] (fp16)
// + Sc[128] + Sd[256]
#define SC_QOFF 0
#define SC_KOFF (128*68)
#define SC_POFF (2*128*68)
#define SC_FLOATS (4*128*68)            // 34816 floats = 139264 B
#define SCORE_SMEM (SC_FLOATS*4 + 128*260*2 + 384*4)   // 207360 bytes

__device__ __forceinline__ uint32_t f2tf32(float f) {
    uint32_t u;
    asm("cvt.rna.tf32.f32 %0, %1;" : "=r"(u) : "f"(f));
    return u;
}

__device__ __forceinline__ void mma_tf32(float c[4], const uint32_t a[4],
                                         const uint32_t b[2]) {
    asm volatile(
        "mma.sync.aligned.m16n8k8.row.col.f32.tf32.tf32.f32 "
        "{%0,%1,%2,%3}, {%4,%5,%6,%7}, {%8,%9}, {%0,%1,%2,%3};"
        : "+f"(c[0]), "+f"(c[1]), "+f"(c[2]), "+f"(c[3])
        : "r"(a[0]), "r"(a[1]), "r"(a[2]), "r"(a[3]), "r"(b[0]), "r"(b[1]));
}

__device__ __forceinline__ void cpa16(uint32_t dst_smem, const void* src) {
    asm volatile("cp.async.cg.shared.global [%0], [%1], 16;"
                 :: "r"(dst_smem), "l"(src));
}
#define CPA_COMMIT() asm volatile("cp.async.commit_group;")
#define CPA_WAIT(n)  asm volatile("cp.async.wait_group %0;" :: "n"(n))

// ---------------------------------------------------------------------------
// TF32 SGEMM, 2-stage pipelined: C = A @ W^T (+bias).
// round_out: store tf32-rounded values (for buffers consumed as raw mma ops).
// ---------------------------------------------------------------------------
__global__ void __launch_bounds__(256, 2)
gemm_tf32(const float* __restrict__ A, const float* __restrict__ W,
          const float* __restrict__ bias, float* __restrict__ C,
          int M, int N, int K, int lda, int ldw, int ldc, int round_out)
{
    __shared__ uint32_t As[2][16][136];
    __shared__ uint32_t Bs[2][16][136];
    const int m0 = blockIdx.y * 128, n0 = blockIdx.x * 128;
    const int t = threadIdx.x, lane = t & 31, warp = t >> 5;
    const int wm = (warp & 1) * 64, wn = (warp >> 1) * 32;
    const int g = lane >> 2, q4 = lane & 3;
    const int r0 = t >> 2, kc = (t & 3) * 4;

    float acc[4][4][4] = {};
    float4 a0, a1, w0, w1;

    auto ldg = [&](int k0) {
        a0 = make_float4(0.f,0.f,0.f,0.f);
        a1 = make_float4(0.f,0.f,0.f,0.f);
        w0 = make_float4(0.f,0.f,0.f,0.f);
        w1 = make_float4(0.f,0.f,0.f,0.f);
        if (m0 + r0      < M) a0 = *(const float4*)(A + (size_t)(m0+r0)*lda + k0 + kc);
        if (m0 + r0 + 64 < M) a1 = *(const float4*)(A + (size_t)(m0+r0+64)*lda + k0 + kc);
        if (n0 + r0      < N) w0 = *(const float4*)(W + (size_t)(n0+r0)*ldw + k0 + kc);
        if (n0 + r0 + 64 < N) w1 = *(const float4*)(W + (size_t)(n0+r0+64)*ldw + k0 + kc);
    };
    auto sts = [&](int buf) {
        As[buf][kc][r0]      = f2tf32(a0.x); As[buf][kc+1][r0]      = f2tf32(a0.y);
        As[buf][kc+2][r0]    = f2tf32(a0.z); As[buf][kc+3][r0]      = f2tf32(a0.w);
        As[buf][kc][r0+64]   = f2tf32(a1.x); As[buf][kc+1][r0+64]   = f2tf32(a1.y);
        As[buf][kc+2][r0+64] = f2tf32(a1.z); As[buf][kc+3][r0+64]   = f2tf32(a1.w);
        Bs[buf][kc][r0]      = f2tf32(w0.x); Bs[buf][kc+1][r0]      = f2tf32(w0.y);
        Bs[buf][kc+2][r0]    = f2tf32(w0.z); Bs[buf][kc+3][r0]      = f2tf32(w0.w);
        Bs[buf][kc][r0+64]   = f2tf32(w1.x); Bs[buf][kc+1][r0+64]   = f2tf32(w1.y);
        Bs[buf][kc+2][r0+64] = f2tf32(w1.z); Bs[buf][kc+3][r0+64]   = f2tf32(w1.w);
    };

    const int nIt = K / 16;
    ldg(0); sts(0);
    __syncthreads();

    for (int it = 0; it < nIt; it++) {
        int buf = it & 1;
        if (it + 1 < nIt) ldg((it + 1) * 16);
        #pragma unroll
        for (int ks = 0; ks < 2; ks++) {
            const int kq = ks * 8;
            uint32_t af[4][4], bf[4][2];
            #pragma unroll
            for (int mi = 0; mi < 4; mi++) {
                int rm = wm + mi * 16;
                af[mi][0] = As[buf][kq + q4][rm + g];
                af[mi][1] = As[buf][kq + q4][rm + 8 + g];
                af[mi][2] = As[buf][kq + 4 + q4][rm + g];
                af[mi][3] = As[buf][kq + 4 + q4][rm + 8 + g];
            }
            #pragma unroll
            for (int ni = 0; ni < 4; ni++) {
                int cn = wn + ni * 8;
                bf[ni][0] = Bs[buf][kq + q4][cn + g];
                bf[ni][1] = Bs[buf][kq + 4 + q4][cn + g];
            }
            #pragma unroll
            for (int mi = 0; mi < 4; mi++)
                #pragma unroll
                for (int ni = 0; ni < 4; ni++)
                    mma_tf32(acc[mi][ni], af[mi], bf[ni]);
        }
        if (it + 1 < nIt) sts(buf ^ 1);
        __syncthreads();
    }

    #pragma unroll
    for (int mi = 0; mi < 4; mi++) {
        int row = m0 + wm + mi * 16 + g;
        #pragma unroll
        for (int ni = 0; ni < 4; ni++) {
            int col = n0 + wn + ni * 8 + 2 * q4;
            float b0 = bias ? bias[col] : 0.f, b1 = bias ? bias[col+1] : 0.f;
            float v0 = acc[mi][ni][0] + b0, v1 = acc[mi][ni][1] + b1;
            float v2 = acc[mi][ni][2] + b0, v3 = acc[mi][ni][3] + b1;
            if (round_out) {
                v0 = __uint_as_float(f2tf32(v0)); v1 = __uint_as_float(f2tf32(v1));
                v2 = __uint_as_float(f2tf32(v2)); v3 = __uint_as_float(f2tf32(v3));
            }
            if (row < M)
                *(float2*)(C + (size_t)row*ldc + col) = make_float2(v0, v1);
            if (row + 8 < M)
                *(float2*)(C + (size_t)(row+8)*ldc + col) = make_float2(v2, v3);
        }
    }
}

// ---------------------------------------------------------------------------
// Score kernel v3: attn[z,q,k] = s*(Q.K) + c[k] + s*(Q.pk[k-q+1023]) + d[j]
// (rank-1 bias folding). Raw tf32-rounded Q/K/P cp.async'd whole-tile into
// smem; BD band -> fp16 D buffer; AC in regs; combine at epilogue.
// 512 threads (16 warps 4x4), occ 1.
// ---------------------------------------------------------------------------
__global__ void __launch_bounds__(512)
score_tc(const float* __restrict__ ub, const float* __restrict__ vbb,
         float* __restrict__ attn)
{
    extern __shared__ char sm_raw[];
    float*  SMF = (float*)sm_raw;
    float*  Qs  = SMF + SC_QOFF;     // [128][68]
    float*  Ks  = SMF + SC_KOFF;     // [128][68]
    float*  Ps  = SMF + SC_POFF;     // [256][68]
    __half* D   = (__half*)(SMF + SC_FLOATS);       // [128][260]
    float*  Sc  = (float*)(D + 128*260);            // [128]
    float*  Sd  = Sc + 128;                         // [256]
    const uint32_t* Qu = (const uint32_t*)Qs;
    const uint32_t* Ku = (const uint32_t*)Ks;
    const uint32_t* Pu = (const uint32_t*)Ps;

    const int z = blockIdx.z, b = z >> 3, h = z & 7;
    const int q0 = blockIdx.y * 128, k0 = blockIdx.x * 128;
    const float* Aq = g_proj + (size_t)b*Lq*QKVq + h*192;
    const float* Bk = Aq + 64;
    const float* Pk = g_pk + h*64;
    float* Cc = attn + (size_t)z * Lq * Lq;
    const int j0 = k0 - q0 + 896;    // band start; rows j0..j0+255 (<=2047 ok)

    const int t = threadIdx.x, lane = t & 31, warp = t >> 5;
    const int wm = (warp & 3) * 32, wn = (warp >> 2) * 32;
    const int g = lane >> 2, q4 = lane & 3;

    const uint32_t smQ = (uint32_t)__cvta_generic_to_shared(Qs);
    const uint32_t smK = (uint32_t)__cvta_generic_to_shared(Ks);
    const uint32_t smP = (uint32_t)__cvta_generic_to_shared(Ps);

    // ---- async loads: Q (g0), P (g1), K (g2) ----
    #pragma unroll
    for (int p = 0; p < 4; p++) {
        int i = t + p * 512, m = i >> 4, k4 = (i & 15) * 4;
        cpa16(smQ + (uint32_t)(m*68 + k4)*4, Aq + (size_t)(q0+m)*QKVq + k4);
    }
    CPA_COMMIT();
    #pragma unroll
    for (int p = 0; p < 8; p++) {
        int i = t + p * 512, m = i >> 4, k4 = (i & 15) * 4;
        cpa16(smP + (uint32_t)(m*68 + k4)*4, Pk + (size_t)(j0+m)*Eq + k4);
    }
    CPA_COMMIT();
    #pragma unroll
    for (int p = 0; p < 4; p++) {
        int i = t + p * 512, m = i >> 4, k4 = (i & 15) * 4;
        cpa16(smK + (uint32_t)(m*68 + k4)*4, Bk + (size_t)(k0+m)*QKVq + k4);
    }
    CPA_COMMIT();

    float acc[2][4][4];
    auto zero_acc = [&]() {
        #pragma unroll
        for (int mi = 0; mi < 2; mi++)
            #pragma unroll
            for (int ni = 0; ni < 4; ni++)
                #pragma unroll
                for (int e = 0; e < 4; e++) acc[mi][ni][e] = 0.f;
    };

    CPA_WAIT(1);          // Q and P arrived
    __syncthreads();

    // d[j] = s * (v . P_j)
    if (t < 256) {
        const float* vv = vbb + h*64;
        float s = 0.f;
        #pragma unroll 8
        for (int dd = 0; dd < 64; dd++) s += vv[dd] * Ps[t*68 + dd];
        Sd[t] = s * SCALEF;
    }
    __syncthreads();

    // ---- BD: two 128-col j-chunks ----
    #pragma unroll 1
    for (int jc = 0; jc < 2; jc++) {
        zero_acc();
        #pragma unroll
        for (int k8 = 0; k8 < 8; k8++) {
            const int kq = k8 * 8;
            uint32_t af[2][4], bf[4][2];
            #pragma unroll
            for (int mi = 0; mi < 2; mi++) {
                int rm = wm + mi * 16;
                af[mi][0] = Qu[(rm+g)*68 + kq + q4];
                af[mi][1] = Qu[(rm+8+g)*68 + kq + q4];
                af[mi][2] = Qu[(rm+g)*68 + kq + 4 + q4];
                af[mi][3] = Qu[(rm+8+g)*68 + kq + 4 + q4];
            }
            #pragma unroll
            for (int ni = 0; ni < 4; ni++) {
                int cn = jc * 128 + wn + ni * 8;
                bf[ni][0] = Pu[(cn+g)*68 + kq + q4];
                bf[ni][1] = Pu[(cn+g)*68 + kq + 4 + q4];
            }
            #pragma unroll
            for (int mi = 0; mi < 2; mi++)
                #pragma unroll
                for (int ni = 0; ni < 4; ni++)
                    mma_tf32(acc[mi][ni], af[mi], bf[ni]);
        }
        #pragma unroll
        for (int mi = 0; mi < 2; mi++) {
            int row = wm + mi * 16 + g;
            #pragma unroll
            for (int ni = 0; ni < 4; ni++) {
                int col = wn + ni * 8 + 2 * q4;
                int jcol = jc * 128 + col;
                D[row*260 + jcol]     = __float2half(SCALEF*acc[mi][ni][0] + Sd[jcol]);
                D[row*260 + jcol+1]   = __float2half(SCALEF*acc[mi][ni][1] + Sd[jcol+1]);
                D[(row+8)*260 + jcol]   = __float2half(SCALEF*acc[mi][ni][2] + Sd[jcol]);
                D[(row+8)*260 + jcol+1] = __float2half(SCALEF*acc[mi][ni][3] + Sd[jcol+1]);
            }
        }
    }

    CPA_WAIT(0);          // K arrived
    __syncthreads();      // also makes D writes visible

    // c[k] = s * (u . K_k)
    if (t < 128) {
        const float* uu = ub + h*64;
        float s = 0.f;
        #pragma unroll 8
        for (int dd = 0; dd < 64; dd++) s += uu[dd] * Ks[t*68 + dd];
        Sc[t] = s * SCALEF;
    }
    __syncthreads();

    // ---- AC ----
    zero_acc();
    #pragma unroll
    for (int k8 = 0; k8 < 8; k8++) {
        const int kq = k8 * 8;
        uint32_t af[2][4], bf[4][2];
        #pragma unroll
        for (int mi = 0; mi < 2; mi++) {
            int rm = wm + mi * 16;
            af[mi][0] = Qu[(rm+g)*68 + kq + q4];
            af[mi][1] = Qu[(rm+8+g)*68 + kq + q4];
            af[mi][2] = Qu[(rm+g)*68 + kq + 4 + q4];
            af[mi][3] = Qu[(rm+8+g)*68 + kq + 4 + q4];
        }
        #pragma unroll
        for (int ni = 0; ni < 4; ni++) {
            int cn = wn + ni * 8;
            bf[ni][0] = Ku[(cn+g)*68 + kq + q4];
            bf[ni][1] = Ku[(cn+g)*68 + kq + 4 + q4];
        }
        #pragma unroll
        for (int mi = 0; mi < 2; mi++)
            #pragma unroll
            for (int ni = 0; ni < 4; ni++)
                mma_tf32(acc[mi][ni], af[mi], bf[ni]);
    }

    // ---- combine: s*AC + c[k] + D[band] ----
    #pragma unroll
    for (int mi = 0; mi < 2; mi++) {
        int row = wm + mi * 16 + g;
        #pragma unroll
        for (int ni = 0; ni < 4; ni++) {
            int c = wn + ni * 8 + 2 * q4;
            int jb = c - row + 127;
            float v0 = SCALEF*acc[mi][ni][0] + Sc[c]   + __half2float(D[row*260 + jb]);
            float v1 = SCALEF*acc[mi][ni][1] + Sc[c+1] + __half2float(D[row*260 + jb+1]);
            *(float2*)(Cc + (size_t)(q0+row)*Lq + k0 + c) = make_float2(v0, v1);
            int row2 = row + 8, jb2 = jb - 8;
            float v2 = SCALEF*acc[mi][ni][2] + Sc[c]   + __half2float(D[row2*260 + jb2]);
            float v3 = SCALEF*acc[mi][ni][3] + Sc[c+1] + __half2float(D[row2*260 + jb2+1]);
            *(float2*)(Cc + (size_t)(q0+row2)*Lq + k0 + c) = make_float2(v2, v3);
        }
    }
}

// ---------------------------------------------------------------------------
// Row softmax in-place (1024 per row, 256 threads/row).
// ---------------------------------------------------------------------------
__global__ void softmax_kernel(float* __restrict__ attn)
{
    float* row = attn + (size_t)blockIdx.x * Lq;
    const int t = threadIdx.x;
    float4 v = *(reinterpret_cast<float4*>(row) + t);

    float m = fmaxf(fmaxf(v.x, v.y), fmaxf(v.z, v.w));
    #pragma unroll
    for (int o = 16; o > 0; o >>= 1) m = fmaxf(m, __shfl_xor_sync(0xffffffffu, m, o));
    __shared__ float red[8];
    if ((t & 31) == 0) red[t >> 5] = m;
    __syncthreads();
    float bm = red[0];
    #pragma unroll
    for (int i = 1; i < 8; i++) bm = fmaxf(bm, red[i]);

    v.x = expf(v.x - bm); v.y = expf(v.y - bm);
    v.z = expf(v.z - bm); v.w = expf(v.w - bm);
    float s = v.x + v.y + v.z + v.w;
    #pragma unroll
    for (int o = 16; o > 0; o >>= 1) s += __shfl_xor_sync(0xffffffffu, s, o);
    __syncthreads();
    if ((t & 31) == 0) red[t >> 5] = s;
    __syncthreads();
    float bs = red[0];
    #pragma unroll
    for (int i = 1; i < 8; i++) bs += red[i];
    float inv = 1.0f / bs;
    v.x *= inv; v.y *= inv; v.z *= inv; v.w *= inv;
    *(reinterpret_cast<float4*>(row) + t) = v;
}

// ---------------------------------------------------------------------------
// ctx = attn @ V via TF32 mma, pipelined. Per z: 1024x64x1024.
// ---------------------------------------------------------------------------
__global__ void __launch_bounds__(256, 2)
ctx_tf32(const float* __restrict__ attn)
{
    const int z = blockIdx.z, b = z >> 3, h = z & 7;
    const float* A  = attn  + (size_t)z * Lq * Lq;
    const float* Vm = g_proj + (size_t)b*Lq*QKVq + h*192 + 128;
    float*       Cm = g_ctx  + (size_t)b*Lq*Eq + h*64;

    __shared__ uint32_t As[2][16][136];
    __shared__ uint32_t Bs[2][16][72];
    const int m0 = blockIdx.y * 128;
    const int t = threadIdx.x, lane = t & 31, warp = t >> 5;
    const int wm = (warp & 3) * 32, wn = (warp >> 2) * 32;
    const int g = lane >> 2, q4 = lane & 3;
    const int r0 = t >> 2, kc = (t & 3) * 4;
    const int br = t >> 4, bc = (t & 15) * 4;

    float acc[2][4][4] = {};
    float4 a0r, a1r, bvr;

    auto ldg = [&](int k0) {
        a0r = *(const float4*)(A + (size_t)(m0+r0)*Lq + k0 + kc);
        a1r = *(const float4*)(A + (size_t)(m0+r0+64)*Lq + k0 + kc);
        bvr = *(const float4*)(Vm + (size_t)(k0+br)*QKVq + bc);
    };
    auto sts = [&](int buf) {
        As[buf][kc][r0]      = f2tf32(a0r.x); As[buf][kc+1][r0]      = f2tf32(a0r.y);
        As[buf][kc+2][r0]    = f2tf32(a0r.z); As[buf][kc+3][r0]      = f2tf32(a0r.w);
        As[buf][kc][r0+64]   = f2tf32(a1r.x); As[buf][kc+1][r0+64]   = f2tf32(a1r.y);
        As[buf][kc+2][r0+64] = f2tf32(a1r.z); As[buf][kc+3][r0+64]   = f2tf32(a1r.w);
        Bs[buf][br][bc]   = f2tf32(bvr.x); Bs[buf][br][bc+1] = f2tf32(bvr.y);
        Bs[buf][br][bc+2] = f2tf32(bvr.z); Bs[buf][br][bc+3] = f2tf32(bvr.w);
    };

    ldg(0); sts(0);
    __syncthreads();

    for (int it = 0; it < 64; it++) {
        int buf = it & 1;
        if (it + 1 < 64) ldg((it + 1) * 16);
        #pragma unroll
        for (int ks = 0; ks < 2; ks++) {
            const int kq = ks * 8;
            uint32_t af[2][4], bf[4][2];
            #pragma unroll
            for (int mi = 0; mi < 2; mi++) {
                int rm = wm + mi * 16;
                af[mi][0] = As[buf][kq + q4][rm + g];
                af[mi][1] = As[buf][kq + q4][rm + 8 + g];
                af[mi][2] = As[buf][kq + 4 + q4][rm + g];
                af[mi][3] = As[buf][kq + 4 + q4][rm + 8 + g];
            }
            #pragma unroll
            for (int ni = 0; ni < 4; ni++) {
                int cn = wn + ni * 8;
                bf[ni][0] = Bs[buf][kq + q4][cn + g];
                bf[ni][1] = Bs[buf][kq + 4 + q4][cn + g];
            }
            #pragma unroll
            for (int mi = 0; mi < 2; mi++)
                #pragma unroll
                for (int ni = 0; ni < 4; ni++)
                    mma_tf32(acc[mi][ni], af[mi], bf[ni]);
        }
        if (it + 1 < 64) sts(buf ^ 1);
        __syncthreads();
    }

    #pragma unroll
    for (int mi = 0; mi < 2; mi++) {
        int row0 = m0 + wm + mi * 16 + g;
        #pragma unroll
        for (int ni = 0; ni < 4; ni++) {
            int col = wn + ni * 8 + 2 * q4;
            *(float2*)(Cm + (size_t)row0*Eq + col) =
                make_float2(acc[mi][ni][0], acc[mi][ni][1]);
            *(float2*)(Cm + (size_t)(row0+8)*Eq + col) =
                make_float2(acc[mi][ni][2], acc[mi][ni][3]);
        }
    }
}

// ---------------------------------------------------------------------------
extern "C" void kernel_launch(void* const* d_in, const int* in_sizes, int n_in,
                              void* d_out, int out_size)
{
    const float* x     = (const float*)d_in[0];
    const float* pos   = (const float*)d_in[1];
    const float* w_in  = (const float*)d_in[2];
    const float* w_pos = (const float*)d_in[3];
    const float* w_out = (const float*)d_in[4];
    const float* b_out = (const float*)d_in[5];
    const float* ub    = (const float*)d_in[6];
    const float* vbb   = (const float*)d_in[7];
    float* out = (float*)d_out;

    float *proj, *pk, *ctx, *attn_fb;
    cudaGetSymbolAddress((void**)&proj,    g_proj);
    cudaGetSymbolAddress((void**)&pk,      g_pk);
    cudaGetSymbolAddress((void**)&ctx,     g_ctx);
    cudaGetSymbolAddress((void**)&attn_fb, g_attn_fb);

    cudaFuncSetAttribute(score_tc, cudaFuncAttributeMaxDynamicSharedMemorySize,
                         SCORE_SMEM);

    const size_t OUT_E  = (size_t)BLq * Eq;
    const size_t ATTN_E = (size_t)Bq * Hq * Lq * Lq;
    float* attn = ((size_t)out_size >= OUT_E + ATTN_E) ? (out + OUT_E) : attn_fb;

    // 1) QKV projection - TF32, output rounded to tf32 (consumed raw by score/ctx)
    gemm_tf32<<<dim3(QKVq/128, BLq/128), 256>>>(x, w_in, nullptr, proj,
                                                BLq, QKVq, Eq, Eq, Eq, QKVq, 1);
    // 2) positional keys - TF32, rounded
    gemm_tf32<<<dim3(Eq/128, (Pq+127)/128), 256>>>(pos, w_pos, nullptr, pk,
                                                   Pq, Eq, Eq, Eq, Eq, Eq, 1);
    // 3) fused AC + shifted BD logits - cp.async whole-tile score kernel
    score_tc<<<dim3(Lq/128, Lq/128, Bq*Hq), 512, SCORE_SMEM>>>(ub, vbb, attn);
    // 4) softmax
    softmax_kernel<<<Bq*Hq*Lq, 256>>>(attn);
    // 5) ctx = attn @ V - TF32
    ctx_tf32<<<dim3(1, Lq/128, Bq*Hq), 256>>>(attn);
    // 6) out projection + bias - TF32 (exact fp32 output)
    gemm_tf32<<<dim3(Eq/128, BLq/128), 256>>>(ctx, w_out, b_out, out,
                                              BLq, Eq, Eq, Eq, Eq, Eq, 0);
}

// round 13
// speedup vs baseline: 1.5076x; 1.2286x over previous
#include <cuda_runtime.h>
#include <cuda_bf16.h>
#include <cuda_fp16.h>
#include <cstdint>
#include <math.h>

#define Bq   8
#define Lq   1024
#define Eq   512
#define Hq   8
#define HDq  64
#define Pq   2047
#define BLq  8192
#define QKVq 1536
#define SCALEF 0.044194173824159216f  // 1/sqrt(512)

__device__ __half g_projh[(size_t)BLq * QKVq];      // qkv projection (fp16)
__device__ __half g_pkh[(size_t)(Pq + 1) * Eq];     // pos keys (fp16), pad row 0
__device__ __half g_vt[(size_t)Bq * Hq * HDq * Lq]; // V transposed [z][n][k]
__device__ __half g_ctxh[(size_t)BLq * Eq];         // context (fp16)
__device__ float  g_attn_fb[(size_t)Bq * Hq * Lq * Lq];

// score smem: Q[128][72h] K[128][72h] P[256][72h] + D[128][260]h + Sc/Sd
#define SCORE_SMEM (128*144 + 128*144 + 256*144 + 128*260*2 + 384*4)  // 141824

__device__ __forceinline__ void mma_f16(float c[4], const uint32_t a[4],
                                        const uint32_t b[2]) {
    asm volatile(
        "mma.sync.aligned.m16n8k16.row.col.f32.f16.f16.f32 "
        "{%0,%1,%2,%3}, {%4,%5,%6,%7}, {%8,%9}, {%0,%1,%2,%3};"
        : "+f"(c[0]), "+f"(c[1]), "+f"(c[2]), "+f"(c[3])
        : "r"(a[0]), "r"(a[1]), "r"(a[2]), "r"(a[3]), "r"(b[0]), "r"(b[1]));
}

__device__ __forceinline__ uint32_t h2u(float x, float y) {
    __half2 h = __floats2half2_rn(x, y);
    return *(uint32_t*)&h;
}

__device__ __forceinline__ void cpa16(uint32_t dst_smem, const void* src) {
    asm volatile("cp.async.cg.shared.global [%0], [%1], 16;"
                 :: "r"(dst_smem), "l"(src));
}
#define CPA_COMMIT() asm volatile("cp.async.commit_group;")
#define CPA_WAIT(n)  asm volatile("cp.async.wait_group %0;" :: "n"(n))

// smem operand layout for gemm kernels: [row][k] halves, row stride 24 halves
// (12 words). Fragment word = row*12 + q4 (+4 for k+8). Banks 12r+q4 distinct.
#define GS 12

// ---------------------------------------------------------------------------
// FP16 GEMM (fp32 inputs): C[M,N] = A @ W^T, C stored as HALF.
// 128x128 tile, BK=16, 256 threads (8 warps 2x4), warp 64x32, 2-stage pipe.
// ---------------------------------------------------------------------------
__global__ void __launch_bounds__(256, 2)
gemm_h(const float* __restrict__ A, const float* __restrict__ W,
       __half* __restrict__ C, int M, int N, int K, int lda, int ldw, int ldc)
{
    __shared__ uint32_t As[2][128 * GS];
    __shared__ uint32_t Bs[2][128 * GS];
    const int m0 = blockIdx.y * 128, n0 = blockIdx.x * 128;
    const int t = threadIdx.x, lane = t & 31, warp = t >> 5;
    const int wm = (warp & 1) * 64, wn = (warp >> 1) * 32;
    const int g = lane >> 2, q4 = lane & 3;
    const int lr = t >> 1, kh = (t & 1) * 8;   // loader row / k-half

    float acc[4][4][4] = {};
    float4 fa0, fa1, fw0, fw1;

    auto ldg = [&](int k0) {
        fa0 = make_float4(0,0,0,0); fa1 = make_float4(0,0,0,0);
        fw0 = make_float4(0,0,0,0); fw1 = make_float4(0,0,0,0);
        if (m0 + lr < M) {
            fa0 = *(const float4*)(A + (size_t)(m0+lr)*lda + k0 + kh);
            fa1 = *(const float4*)(A + (size_t)(m0+lr)*lda + k0 + kh + 4);
        }
        if (n0 + lr < N) {
            fw0 = *(const float4*)(W + (size_t)(n0+lr)*ldw + k0 + kh);
            fw1 = *(const float4*)(W + (size_t)(n0+lr)*ldw + k0 + kh + 4);
        }
    };
    auto sts = [&](int buf) {
        int w = lr * GS + (kh >> 1);
        As[buf][w]   = h2u(fa0.x, fa0.y); As[buf][w+1] = h2u(fa0.z, fa0.w);
        As[buf][w+2] = h2u(fa1.x, fa1.y); As[buf][w+3] = h2u(fa1.z, fa1.w);
        Bs[buf][w]   = h2u(fw0.x, fw0.y); Bs[buf][w+1] = h2u(fw0.z, fw0.w);
        Bs[buf][w+2] = h2u(fw1.x, fw1.y); Bs[buf][w+3] = h2u(fw1.z, fw1.w);
    };

    const int nIt = K / 16;
    ldg(0); sts(0);
    __syncthreads();

    for (int it = 0; it < nIt; it++) {
        int buf = it & 1;
        if (it + 1 < nIt) ldg((it + 1) * 16);
        uint32_t af[4][4], bf[4][2];
        #pragma unroll
        for (int mi = 0; mi < 4; mi++) {
            int rm = wm + mi * 16;
            af[mi][0] = As[buf][(rm+g)*GS + q4];
            af[mi][1] = As[buf][(rm+8+g)*GS + q4];
            af[mi][2] = As[buf][(rm+g)*GS + 4 + q4];
            af[mi][3] = As[buf][(rm+8+g)*GS + 4 + q4];
        }
        #pragma unroll
        for (int ni = 0; ni < 4; ni++) {
            int cn = wn + ni * 8;
            bf[ni][0] = Bs[buf][(cn+g)*GS + q4];
            bf[ni][1] = Bs[buf][(cn+g)*GS + 4 + q4];
        }
        #pragma unroll
        for (int mi = 0; mi < 4; mi++)
            #pragma unroll
            for (int ni = 0; ni < 4; ni++)
                mma_f16(acc[mi][ni], af[mi], bf[ni]);
        if (it + 1 < nIt) sts(buf ^ 1);
        __syncthreads();
    }

    #pragma unroll
    for (int mi = 0; mi < 4; mi++) {
        int row = m0 + wm + mi * 16 + g;
        #pragma unroll
        for (int ni = 0; ni < 4; ni++) {
            int col = n0 + wn + ni * 8 + 2 * q4;
            if (row < M)
                *(uint32_t*)(C + (size_t)row*ldc + col) =
                    h2u(acc[mi][ni][0], acc[mi][ni][1]);
            if (row + 8 < M)
                *(uint32_t*)(C + (size_t)(row+8)*ldc + col) =
                    h2u(acc[mi][ni][2], acc[mi][ni][3]);
        }
    }
}

// ---------------------------------------------------------------------------
// V transpose: g_projh v-part [l][n] -> g_vt [z][n][l].
// ---------------------------------------------------------------------------
__global__ void vtrans()
{
    __shared__ __half T[64][72];
    const int z = blockIdx.y, b = z >> 3, h = z & 7;
    const int l0 = blockIdx.x * 64;
    const int t = threadIdx.x;
    const __half* src = g_projh + (size_t)(b * Lq) * QKVq + h*192 + 128;

    for (int i = t; i < 512; i += 128) {
        int row = i >> 3, ch = i & 7;
        uint4 v = *(const uint4*)(src + (size_t)(l0+row)*QKVq + ch*8);
        const __half* hv = (const __half*)&v;
        #pragma unroll
        for (int j = 0; j < 8; j++) T[ch*8 + j][row] = hv[j];
    }
    __syncthreads();
    for (int i = t; i < 512; i += 128) {
        int n = i >> 3, ch = i & 7;
        uint4 v; __half* hv = (__half*)&v;
        #pragma unroll
        for (int j = 0; j < 8; j++) hv[j] = T[n][ch*8 + j];
        *(uint4*)(g_vt + ((size_t)z*64 + n)*Lq + l0 + ch*8) = v;
    }
}

// ---------------------------------------------------------------------------
// Score kernel (fp16 mma): attn = s*(Q.K) + c[k] + s*(Q.P[band]) + d[j].
// Whole half tiles cp.async'd; row stride 72 halves (36 words).
// 512 threads (16 warps 4x4), occ 1.
// ---------------------------------------------------------------------------
#define SS 36
__global__ void __launch_bounds__(512)
score_h(const float* __restrict__ ub, const float* __restrict__ vbb,
        float* __restrict__ attn)
{
    extern __shared__ char sm_raw[];
    __half* Qh = (__half*)sm_raw;                 // [128][72]
    __half* Kh = Qh + 128*72;                     // [128][72]
    __half* Ph = Kh + 128*72;                     // [256][72]
    __half* D  = Ph + 256*72;                     // [128][260]
    float*  Sc = (float*)(D + 128*260);           // [128]
    float*  Sd = Sc + 128;                        // [256]
    const uint32_t* Qu = (const uint32_t*)Qh;
    const uint32_t* Ku = (const uint32_t*)Kh;
    const uint32_t* Pu = (const uint32_t*)Ph;

    const int z = blockIdx.z, b = z >> 3, h = z & 7;
    const int q0 = blockIdx.y * 128, k0 = blockIdx.x * 128;
    const __half* Aq = g_projh + (size_t)b*Lq*QKVq + h*192;
    const __half* Bk = Aq + 64;
    const __half* Pk = g_pkh + h*64;
    float* Cc = attn + (size_t)z * Lq * Lq;
    const int j0 = k0 - q0 + 896;

    const int t = threadIdx.x, lane = t & 31, warp = t >> 5;
    const int wm = (warp & 3) * 32, wn = (warp >> 2) * 32;
    const int g = lane >> 2, q4 = lane & 3;

    const uint32_t smQ = (uint32_t)__cvta_generic_to_shared(Qh);
    const uint32_t smK = (uint32_t)__cvta_generic_to_shared(Kh);
    const uint32_t smP = (uint32_t)__cvta_generic_to_shared(Ph);

    // Q (group 2 pending), P (group 1), K (group 0)
    #pragma unroll
    for (int p = 0; p < 2; p++) {
        int i = t + p * 512, m = i >> 3, c8 = (i & 7) * 8;
        cpa16(smQ + (uint32_t)(m*144 + c8*2), Aq + (size_t)(q0+m)*QKVq + c8);
    }
    CPA_COMMIT();
    #pragma unroll
    for (int p = 0; p < 4; p++) {
        int i = t + p * 512, m = i >> 3, c8 = (i & 7) * 8;
        cpa16(smP + (uint32_t)(m*144 + c8*2), Pk + (size_t)(j0+m)*Eq + c8);
    }
    CPA_COMMIT();
    #pragma unroll
    for (int p = 0; p < 2; p++) {
        int i = t + p * 512, m = i >> 3, c8 = (i & 7) * 8;
        cpa16(smK + (uint32_t)(m*144 + c8*2), Bk + (size_t)(k0+m)*QKVq + c8);
    }
    CPA_COMMIT();

    float acc[2][4][4];
    auto zero_acc = [&]() {
        #pragma unroll
        for (int mi = 0; mi < 2; mi++)
            #pragma unroll
            for (int ni = 0; ni < 4; ni++)
                #pragma unroll
                for (int e = 0; e < 4; e++) acc[mi][ni][e] = 0.f;
    };

    CPA_WAIT(1);
    __syncthreads();

    if (t < 256) {
        const float* vv = vbb + h*64;
        float s = 0.f;
        #pragma unroll 8
        for (int dd = 0; dd < 64; dd++) s += vv[dd] * __half2float(Ph[t*72 + dd]);
        Sd[t] = s * SCALEF;
    }
    __syncthreads();

    // ---- BD: two 128-col j-chunks, K=64 -> 4 k16 steps ----
    #pragma unroll 1
    for (int jc = 0; jc < 2; jc++) {
        zero_acc();
        #pragma unroll
        for (int s = 0; s < 4; s++) {
            const int kb = s * 8;
            uint32_t af[2][4], bf[4][2];
            #pragma unroll
            for (int mi = 0; mi < 2; mi++) {
                int rm = wm + mi * 16;
                af[mi][0] = Qu[(rm+g)*SS + kb + q4];
                af[mi][1] = Qu[(rm+8+g)*SS + kb + q4];
                af[mi][2] = Qu[(rm+g)*SS + kb + 4 + q4];
                af[mi][3] = Qu[(rm+8+g)*SS + kb + 4 + q4];
            }
            #pragma unroll
            for (int ni = 0; ni < 4; ni++) {
                int cn = jc * 128 + wn + ni * 8;
                bf[ni][0] = Pu[(cn+g)*SS + kb + q4];
                bf[ni][1] = Pu[(cn+g)*SS + kb + 4 + q4];
            }
            #pragma unroll
            for (int mi = 0; mi < 2; mi++)
                #pragma unroll
                for (int ni = 0; ni < 4; ni++)
                    mma_f16(acc[mi][ni], af[mi], bf[ni]);
        }
        #pragma unroll
        for (int mi = 0; mi < 2; mi++) {
            int row = wm + mi * 16 + g;
            #pragma unroll
            for (int ni = 0; ni < 4; ni++) {
                int col = wn + ni * 8 + 2 * q4;
                int jcol = jc * 128 + col;
                D[row*260 + jcol]       = __float2half(SCALEF*acc[mi][ni][0] + Sd[jcol]);
                D[row*260 + jcol+1]     = __float2half(SCALEF*acc[mi][ni][1] + Sd[jcol+1]);
                D[(row+8)*260 + jcol]   = __float2half(SCALEF*acc[mi][ni][2] + Sd[jcol]);
                D[(row+8)*260 + jcol+1] = __float2half(SCALEF*acc[mi][ni][3] + Sd[jcol+1]);
            }
        }
    }

    CPA_WAIT(0);
    __syncthreads();

    if (t < 128) {
        const float* uu = ub + h*64;
        float s = 0.f;
        #pragma unroll 8
        for (int dd = 0; dd < 64; dd++) s += uu[dd] * __half2float(Kh[t*72 + dd]);
        Sc[t] = s * SCALEF;
    }
    __syncthreads();

    // ---- AC ----
    zero_acc();
    #pragma unroll
    for (int s = 0; s < 4; s++) {
        const int kb = s * 8;
        uint32_t af[2][4], bf[4][2];
        #pragma unroll
        for (int mi = 0; mi < 2; mi++) {
            int rm = wm + mi * 16;
            af[mi][0] = Qu[(rm+g)*SS + kb + q4];
            af[mi][1] = Qu[(rm+8+g)*SS + kb + q4];
            af[mi][2] = Qu[(rm+g)*SS + kb + 4 + q4];
            af[mi][3] = Qu[(rm+8+g)*SS + kb + 4 + q4];
        }
        #pragma unroll
        for (int ni = 0; ni < 4; ni++) {
            int cn = wn + ni * 8;
            bf[ni][0] = Ku[(cn+g)*SS + kb + q4];
            bf[ni][1] = Ku[(cn+g)*SS + kb + 4 + q4];
        }
        #pragma unroll
        for (int mi = 0; mi < 2; mi++)
            #pragma unroll
            for (int ni = 0; ni < 4; ni++)
                mma_f16(acc[mi][ni], af[mi], bf[ni]);
    }

    // ---- combine ----
    #pragma unroll
    for (int mi = 0; mi < 2; mi++) {
        int row = wm + mi * 16 + g;
        #pragma unroll
        for (int ni = 0; ni < 4; ni++) {
            int c = wn + ni * 8 + 2 * q4;
            int jb = c - row + 127;
            float v0 = SCALEF*acc[mi][ni][0] + Sc[c]   + __half2float(D[row*260 + jb]);
            float v1 = SCALEF*acc[mi][ni][1] + Sc[c+1] + __half2float(D[row*260 + jb+1]);
            *(float2*)(Cc + (size_t)(q0+row)*Lq + k0 + c) = make_float2(v0, v1);
            int row2 = row + 8, jb2 = jb - 8;
            float v2 = SCALEF*acc[mi][ni][2] + Sc[c]   + __half2float(D[row2*260 + jb2]);
            float v3 = SCALEF*acc[mi][ni][3] + Sc[c+1] + __half2float(D[row2*260 + jb2+1]);
            *(float2*)(Cc + (size_t)(q0+row2)*Lq + k0 + c) = make_float2(v2, v3);
        }
    }
}

// ---------------------------------------------------------------------------
// Row softmax in-place (fp32).
// ---------------------------------------------------------------------------
__global__ void softmax_kernel(float* __restrict__ attn)
{
    float* row = attn + (size_t)blockIdx.x * Lq;
    const int t = threadIdx.x;
    float4 v = *(reinterpret_cast<float4*>(row) + t);

    float m = fmaxf(fmaxf(v.x, v.y), fmaxf(v.z, v.w));
    #pragma unroll
    for (int o = 16; o > 0; o >>= 1) m = fmaxf(m, __shfl_xor_sync(0xffffffffu, m, o));
    __shared__ float red[8];
    if ((t & 31) == 0) red[t >> 5] = m;
    __syncthreads();
    float bm = red[0];
    #pragma unroll
    for (int i = 1; i < 8; i++) bm = fmaxf(bm, red[i]);

    v.x = expf(v.x - bm); v.y = expf(v.y - bm);
    v.z = expf(v.z - bm); v.w = expf(v.w - bm);
    float s = v.x + v.y + v.z + v.w;
    #pragma unroll
    for (int o = 16; o > 0; o >>= 1) s += __shfl_xor_sync(0xffffffffu, s, o);
    __syncthreads();
    if ((t & 31) == 0) red[t >> 5] = s;
    __syncthreads();
    float bs = red[0];
    #pragma unroll
    for (int i = 1; i < 8; i++) bs += red[i];
    float inv = 1.0f / bs;
    v.x *= inv; v.y *= inv; v.z *= inv; v.w *= inv;
    *(reinterpret_cast<float4*>(row) + t) = v;
}

// ---------------------------------------------------------------------------
// ctx = attn @ V (fp16 mma). A=attn fp32 (cvt), B=g_vt half [n][k].
// 128(M)x64(N) tile, BK=16, 256 threads (8 warps 4x2), warp 32x32.
// Output HALF to g_ctxh.
// ---------------------------------------------------------------------------
__global__ void __launch_bounds__(256, 2)
ctx_h(const float* __restrict__ attn)
{
    const int z = blockIdx.z, b = z >> 3, h = z & 7;
    const float*  A  = attn + (size_t)z * Lq * Lq;
    const __half* Vt = g_vt + (size_t)z * 64 * Lq;   // [n][k]
    __half*       Cm = g_ctxh + (size_t)b*Lq*Eq + h*64;

    __shared__ uint32_t As[2][128 * GS];
    __shared__ uint32_t Bs[2][64 * GS];
    const int m0 = blockIdx.y * 128;
    const int t = threadIdx.x, lane = t & 31, warp = t >> 5;
    const int wm = (warp & 3) * 32, wn = (warp >> 2) * 32;
    const int g = lane >> 2, q4 = lane & 3;
    const int lr = t >> 1, kh = (t & 1) * 8;

    float acc[2][4][4] = {};
    float4 fa0, fa1;
    uint4  bv;

    auto ldg = [&](int k0) {
        fa0 = *(const float4*)(A + (size_t)(m0+lr)*Lq + k0 + kh);
        fa1 = *(const float4*)(A + (size_t)(m0+lr)*Lq + k0 + kh + 4);
        if (t < 128)
            bv = *(const uint4*)(Vt + (size_t)(t >> 1)*Lq + k0 + kh);
    };
    auto sts = [&](int buf) {
        int w = lr * GS + (kh >> 1);
        As[buf][w]   = h2u(fa0.x, fa0.y); As[buf][w+1] = h2u(fa0.z, fa0.w);
        As[buf][w+2] = h2u(fa1.x, fa1.y); As[buf][w+3] = h2u(fa1.z, fa1.w);
        if (t < 128) {
            int wb = (t >> 1) * GS + (kh >> 1);
            Bs[buf][wb]   = bv.x; Bs[buf][wb+1] = bv.y;
            Bs[buf][wb+2] = bv.z; Bs[buf][wb+3] = bv.w;
        }
    };

    ldg(0); sts(0);
    __syncthreads();

    for (int it = 0; it < 64; it++) {
        int buf = it & 1;
        if (it + 1 < 64) ldg((it + 1) * 16);
        uint32_t af[2][4], bf[4][2];
        #pragma unroll
        for (int mi = 0; mi < 2; mi++) {
            int rm = wm + mi * 16;
            af[mi][0] = As[buf][(rm+g)*GS + q4];
            af[mi][1] = As[buf][(rm+8+g)*GS + q4];
            af[mi][2] = As[buf][(rm+g)*GS + 4 + q4];
            af[mi][3] = As[buf][(rm+8+g)*GS + 4 + q4];
        }
        #pragma unroll
        for (int ni = 0; ni < 4; ni++) {
            int cn = wn + ni * 8;
            bf[ni][0] = Bs[buf][(cn+g)*GS + q4];
            bf[ni][1] = Bs[buf][(cn+g)*GS + 4 + q4];
        }
        #pragma unroll
        for (int mi = 0; mi < 2; mi++)
            #pragma unroll
            for (int ni = 0; ni < 4; ni++)
                mma_f16(acc[mi][ni], af[mi], bf[ni]);
        if (it + 1 < 64) sts(buf ^ 1);
        __syncthreads();
    }

    #pragma unroll
    for (int mi = 0; mi < 2; mi++) {
        int row = m0 + wm + mi * 16 + g;
        #pragma unroll
        for (int ni = 0; ni < 4; ni++) {
            int col = wn + ni * 8 + 2 * q4;
            *(uint32_t*)(Cm + (size_t)row*Eq + col) =
                h2u(acc[mi][ni][0], acc[mi][ni][1]);
            *(uint32_t*)(Cm + (size_t)(row+8)*Eq + col) =
                h2u(acc[mi][ni][2], acc[mi][ni][3]);
        }
    }
}

// ---------------------------------------------------------------------------
// Out projection: out = ctxh @ W^T + bias. A half in gmem, W fp32, out fp32.
// ---------------------------------------------------------------------------
__global__ void __launch_bounds__(256, 2)
gemm_out(const __half* __restrict__ A, const float* __restrict__ W,
         const float* __restrict__ bias, float* __restrict__ C,
         int M, int N, int K)
{
    __shared__ uint32_t As[2][128 * GS];
    __shared__ uint32_t Bs[2][128 * GS];
    const int m0 = blockIdx.y * 128, n0 = blockIdx.x * 128;
    const int t = threadIdx.x, lane = t & 31, warp = t >> 5;
    const int wm = (warp & 1) * 64, wn = (warp >> 1) * 32;
    const int g = lane >> 2, q4 = lane & 3;
    const int lr = t >> 1, kh = (t & 1) * 8;

    float acc[4][4][4] = {};
    uint4 av;
    float4 fw0, fw1;

    auto ldg = [&](int k0) {
        av  = *(const uint4*)(A + (size_t)(m0+lr)*K + k0 + kh);
        fw0 = *(const float4*)(W + (size_t)(n0+lr)*K + k0 + kh);
        fw1 = *(const float4*)(W + (size_t)(n0+lr)*K + k0 + kh + 4);
    };
    auto sts = [&](int buf) {
        int w = lr * GS + (kh >> 1);
        As[buf][w]   = av.x; As[buf][w+1] = av.y;
        As[buf][w+2] = av.z; As[buf][w+3] = av.w;
        Bs[buf][w]   = h2u(fw0.x, fw0.y); Bs[buf][w+1] = h2u(fw0.z, fw0.w);
        Bs[buf][w+2] = h2u(fw1.x, fw1.y); Bs[buf][w+3] = h2u(fw1.z, fw1.w);
    };

    const int nIt = K / 16;
    ldg(0); sts(0);
    __syncthreads();

    for (int it = 0; it < nIt; it++) {
        int buf = it & 1;
        if (it + 1 < nIt) ldg((it + 1) * 16);
        uint32_t af[4][4], bf[4][2];
        #pragma unroll
        for (int mi = 0; mi < 4; mi++) {
            int rm = wm + mi * 16;
            af[mi][0] = As[buf][(rm+g)*GS + q4];
            af[mi][1] = As[buf][(rm+8+g)*GS + q4];
            af[mi][2] = As[buf][(rm+g)*GS + 4 + q4];
            af[mi][3] = As[buf][(rm+8+g)*GS + 4 + q4];
        }
        #pragma unroll
        for (int ni = 0; ni < 4; ni++) {
            int cn = wn + ni * 8;
            bf[ni][0] = Bs[buf][(cn+g)*GS + q4];
            bf[ni][1] = Bs[buf][(cn+g)*GS + 4 + q4];
        }
        #pragma unroll
        for (int mi = 0; mi < 4; mi++)
            #pragma unroll
            for (int ni = 0; ni < 4; ni++)
                mma_f16(acc[mi][ni], af[mi], bf[ni]);
        if (it + 1 < nIt) sts(buf ^ 1);
        __syncthreads();
    }

    #pragma unroll
    for (int mi = 0; mi < 4; mi++) {
        int row = m0 + wm + mi * 16 + g;
        #pragma unroll
        for (int ni = 0; ni < 4; ni++) {
            int col = n0 + wn + ni * 8 + 2 * q4;
            float b0 = bias[col], b1 = bias[col+1];
            *(float2*)(C + (size_t)row*N + col) =
                make_float2(acc[mi][ni][0] + b0, acc[mi][ni][1] + b1);
            *(float2*)(C + (size_t)(row+8)*N + col) =
                make_float2(acc[mi][ni][2] + b0, acc[mi][ni][3] + b1);
        }
    }
}

// ---------------------------------------------------------------------------
extern "C" void kernel_launch(void* const* d_in, const int* in_sizes, int n_in,
                              void* d_out, int out_size)
{
    const float* x     = (const float*)d_in[0];
    const float* pos   = (const float*)d_in[1];
    const float* w_in  = (const float*)d_in[2];
    const float* w_pos = (const float*)d_in[3];
    const float* w_out = (const float*)d_in[4];
    const float* b_out = (const float*)d_in[5];
    const float* ub    = (const float*)d_in[6];
    const float* vbb   = (const float*)d_in[7];
    float* out = (float*)d_out;

    __half *projh, *pkh, *ctxh;
    float *attn_fb;
    cudaGetSymbolAddress((void**)&projh,   g_projh);
    cudaGetSymbolAddress((void**)&pkh,     g_pkh);
    cudaGetSymbolAddress((void**)&ctxh,    g_ctxh);
    cudaGetSymbolAddress((void**)&attn_fb, g_attn_fb);

    cudaFuncSetAttribute(score_h, cudaFuncAttributeMaxDynamicSharedMemorySize,
                         SCORE_SMEM);

    const size_t OUT_E  = (size_t)BLq * Eq;
    const size_t ATTN_E = (size_t)Bq * Hq * Lq * Lq;
    float* attn = ((size_t)out_size >= OUT_E + ATTN_E) ? (out + OUT_E) : attn_fb;

    // 1) QKV projection -> fp16
    gemm_h<<<dim3(QKVq/128, BLq/128), 256>>>(x, w_in, projh,
                                             BLq, QKVq, Eq, Eq, Eq, QKVq);
    // 2) positional keys -> fp16
    gemm_h<<<dim3(Eq/128, (Pq+127)/128), 256>>>(pos, w_pos, pkh,
                                                Pq, Eq, Eq, Eq, Eq, Eq);
    // 3) V transpose for ctx B operand
    vtrans<<<dim3(Lq/64, Bq*Hq), 128>>>();
    // 4) fused AC + shifted BD logits (fp16 mma)
    score_h<<<dim3(Lq/128, Lq/128, Bq*Hq), 512, SCORE_SMEM>>>(ub, vbb, attn);
    // 5) softmax (fp32)
    softmax_kernel<<<Bq*Hq*Lq, 256>>>(attn);
    // 6) ctx = attn @ V (fp16 mma) -> fp16
    ctx_h<<<dim3(1, Lq/128, Bq*Hq), 256>>>(attn);
    // 7) out projection + bias (fp16 mma, fp32 out)
    gemm_out<<<dim3(Eq/128, BLq/128), 256>>>(ctxh, w_out, b_out, out,
                                             BLq, Eq, Eq);
}

// round 14
// speedup vs baseline: 1.5748x; 1.0446x over previous
#include <cuda_runtime.h>
#include <cuda_bf16.h>
#include <cuda_fp16.h>
#include <cstdint>
#include <math.h>

#define Bq   8
#define Lq   1024
#define Eq   512
#define Hq   8
#define HDq  64
#define Pq   2047
#define BLq  8192
#define QKVq 1536
#define SCALEF 0.044194173824159216f  // 1/sqrt(512)

__device__ __half g_projh[(size_t)BLq * QKVq];      // qkv projection (fp16)
__device__ __half g_pkh[(size_t)(Pq + 1) * Eq];     // pos keys (fp16), pad row 0
__device__ __half g_vt[(size_t)Bq * Hq * HDq * Lq]; // V transposed [z][n][k]
__device__ __half g_ctxh[(size_t)BLq * Eq];         // context (fp16)
__device__ float  g_attn_fb[(size_t)Bq * Hq * Lq * Lq];

// score smem: Q[128][72h] K[128][72h] P[256][72h] + D[128][260]h + Sc/Sd
#define SCORE_SMEM (128*144 + 128*144 + 256*144 + 128*260*2 + 384*4)  // 141824

__device__ __forceinline__ void mma_f16(float c[4], const uint32_t a[4],
                                        const uint32_t b[2]) {
    asm volatile(
        "mma.sync.aligned.m16n8k16.row.col.f32.f16.f16.f32 "
        "{%0,%1,%2,%3}, {%4,%5,%6,%7}, {%8,%9}, {%0,%1,%2,%3};"
        : "+f"(c[0]), "+f"(c[1]), "+f"(c[2]), "+f"(c[3])
        : "r"(a[0]), "r"(a[1]), "r"(a[2]), "r"(a[3]), "r"(b[0]), "r"(b[1]));
}

__device__ __forceinline__ void ldsm4(uint32_t r[4], uint32_t addr) {
    asm volatile("ldmatrix.sync.aligned.m8n8.x4.shared.b16 {%0,%1,%2,%3}, [%4];"
                 : "=r"(r[0]), "=r"(r[1]), "=r"(r[2]), "=r"(r[3]) : "r"(addr));
}

__device__ __forceinline__ uint32_t h2u(float x, float y) {
    __half2 h = __floats2half2_rn(x, y);
    return *(uint32_t*)&h;
}

__device__ __forceinline__ void cpa16(uint32_t dst_smem, const void* src) {
    asm volatile("cp.async.cg.shared.global [%0], [%1], 16;"
                 :: "r"(dst_smem), "l"(src));
}
#define CPA_COMMIT() asm volatile("cp.async.commit_group;")
#define CPA_WAIT(n)  asm volatile("cp.async.wait_group %0;" :: "n"(n))

// gemm smem layout: [row][k] halves, row stride 24 halves (12 words, 48 B).
#define GS 12

// ---------------------------------------------------------------------------
// FP16 GEMM (fp32 inputs): C[M,N] = A @ W^T, C stored as HALF.
// 128x128 tile, BK=16, 256 threads (8 warps 2x4), warp 64x32, ldmatrix.
// ---------------------------------------------------------------------------
__global__ void __launch_bounds__(256, 2)
gemm_h(const float* __restrict__ A, const float* __restrict__ W,
       __half* __restrict__ C, int M, int N, int K, int lda, int ldw, int ldc)
{
    __shared__ uint32_t As[2][128 * GS];
    __shared__ uint32_t Bs[2][128 * GS];
    const int m0 = blockIdx.y * 128, n0 = blockIdx.x * 128;
    const int t = threadIdx.x, lane = t & 31, warp = t >> 5;
    const int wm = (warp & 1) * 64, wn = (warp >> 1) * 32;
    const int g = lane >> 2, q4 = lane & 3;
    const int lr = t >> 1, kh = (t & 1) * 8;

    // ldmatrix lane addressing (halves)
    const int aRow = lane & 15, aK = (lane >> 4) << 3;
    const int bRow = (lane & 7) + ((lane >> 4) << 3), bK = ((lane >> 3) & 1) << 3;

    float acc[4][4][4] = {};
    float4 fa0, fa1, fw0, fw1;

    auto ldg = [&](int k0) {
        fa0 = make_float4(0,0,0,0); fa1 = make_float4(0,0,0,0);
        fw0 = make_float4(0,0,0,0); fw1 = make_float4(0,0,0,0);
        if (m0 + lr < M) {
            fa0 = *(const float4*)(A + (size_t)(m0+lr)*lda + k0 + kh);
            fa1 = *(const float4*)(A + (size_t)(m0+lr)*lda + k0 + kh + 4);
        }
        if (n0 + lr < N) {
            fw0 = *(const float4*)(W + (size_t)(n0+lr)*ldw + k0 + kh);
            fw1 = *(const float4*)(W + (size_t)(n0+lr)*ldw + k0 + kh + 4);
        }
    };
    auto sts = [&](int buf) {
        int w = lr * GS + (kh >> 1);
        As[buf][w]   = h2u(fa0.x, fa0.y); As[buf][w+1] = h2u(fa0.z, fa0.w);
        As[buf][w+2] = h2u(fa1.x, fa1.y); As[buf][w+3] = h2u(fa1.z, fa1.w);
        Bs[buf][w]   = h2u(fw0.x, fw0.y); Bs[buf][w+1] = h2u(fw0.z, fw0.w);
        Bs[buf][w+2] = h2u(fw1.x, fw1.y); Bs[buf][w+3] = h2u(fw1.z, fw1.w);
    };

    const int nIt = K / 16;
    ldg(0); sts(0);
    __syncthreads();

    for (int it = 0; it < nIt; it++) {
        int buf = it & 1;
        if (it + 1 < nIt) ldg((it + 1) * 16);
        uint32_t aSm = (uint32_t)__cvta_generic_to_shared(&As[buf][0]);
        uint32_t bSm = (uint32_t)__cvta_generic_to_shared(&Bs[buf][0]);
        uint32_t af[4][4], bf[2][4];
        #pragma unroll
        for (int mi = 0; mi < 4; mi++)
            ldsm4(af[mi], aSm + ((wm + mi*16 + aRow)*24 + aK)*2);
        #pragma unroll
        for (int nj = 0; nj < 2; nj++)
            ldsm4(bf[nj], bSm + ((wn + nj*16 + bRow)*24 + bK)*2);
        #pragma unroll
        for (int mi = 0; mi < 4; mi++)
            #pragma unroll
            for (int ni = 0; ni < 4; ni++)
                mma_f16(acc[mi][ni], af[mi], &bf[ni >> 1][(ni & 1) * 2]);
        if (it + 1 < nIt) sts(buf ^ 1);
        __syncthreads();
    }

    #pragma unroll
    for (int mi = 0; mi < 4; mi++) {
        int row = m0 + wm + mi * 16 + g;
        #pragma unroll
        for (int ni = 0; ni < 4; ni++) {
            int col = n0 + wn + ni * 8 + 2 * q4;
            if (row < M)
                *(uint32_t*)(C + (size_t)row*ldc + col) =
                    h2u(acc[mi][ni][0], acc[mi][ni][1]);
            if (row + 8 < M)
                *(uint32_t*)(C + (size_t)(row+8)*ldc + col) =
                    h2u(acc[mi][ni][2], acc[mi][ni][3]);
        }
    }
}

// ---------------------------------------------------------------------------
// V transpose: g_projh v-part [l][n] -> g_vt [z][n][l].
// ---------------------------------------------------------------------------
__global__ void vtrans()
{
    __shared__ __half T[64][72];
    const int z = blockIdx.y, b = z >> 3, h = z & 7;
    const int l0 = blockIdx.x * 64;
    const int t = threadIdx.x;
    const __half* src = g_projh + (size_t)(b * Lq) * QKVq + h*192 + 128;

    for (int i = t; i < 512; i += 128) {
        int row = i >> 3, ch = i & 7;
        uint4 v = *(const uint4*)(src + (size_t)(l0+row)*QKVq + ch*8);
        const __half* hv = (const __half*)&v;
        #pragma unroll
        for (int j = 0; j < 8; j++) T[ch*8 + j][row] = hv[j];
    }
    __syncthreads();
    for (int i = t; i < 512; i += 128) {
        int n = i >> 3, ch = i & 7;
        uint4 v; __half* hv = (__half*)&v;
        #pragma unroll
        for (int j = 0; j < 8; j++) hv[j] = T[n][ch*8 + j];
        *(uint4*)(g_vt + ((size_t)z*64 + n)*Lq + l0 + ch*8) = v;
    }
}

// ---------------------------------------------------------------------------
// Score kernel (fp16 mma + ldmatrix): attn = s*(Q.K)+c[k]+s*(Q.P[band])+d[j].
// Row stride 72 halves. 512 threads (16 warps 4x4), occ 1.
// ---------------------------------------------------------------------------
__global__ void __launch_bounds__(512)
score_h(const float* __restrict__ ub, const float* __restrict__ vbb,
        float* __restrict__ attn)
{
    extern __shared__ char sm_raw[];
    __half* Qh = (__half*)sm_raw;                 // [128][72]
    __half* Kh = Qh + 128*72;                     // [128][72]
    __half* Ph = Kh + 128*72;                     // [256][72]
    __half* D  = Ph + 256*72;                     // [128][260]
    float*  Sc = (float*)(D + 128*260);           // [128]
    float*  Sd = Sc + 128;                        // [256]

    const int z = blockIdx.z, b = z >> 3, h = z & 7;
    const int q0 = blockIdx.y * 128, k0 = blockIdx.x * 128;
    const __half* Aq = g_projh + (size_t)b*Lq*QKVq + h*192;
    const __half* Bk = Aq + 64;
    const __half* Pk = g_pkh + h*64;
    float* Cc = attn + (size_t)z * Lq * Lq;
    const int j0 = k0 - q0 + 896;

    const int t = threadIdx.x, lane = t & 31, warp = t >> 5;
    const int wm = (warp & 3) * 32, wn = (warp >> 2) * 32;
    const int g = lane >> 2, q4 = lane & 3;

    const int aRow = lane & 15, aK = (lane >> 4) << 3;
    const int bRow = (lane & 7) + ((lane >> 4) << 3), bK = ((lane >> 3) & 1) << 3;

    const uint32_t smQ = (uint32_t)__cvta_generic_to_shared(Qh);
    const uint32_t smK = (uint32_t)__cvta_generic_to_shared(Kh);
    const uint32_t smP = (uint32_t)__cvta_generic_to_shared(Ph);

    // Q (group 2 pending), P (group 1), K (group 0)
    #pragma unroll
    for (int p = 0; p < 2; p++) {
        int i = t + p * 512, m = i >> 3, c8 = (i & 7) * 8;
        cpa16(smQ + (uint32_t)(m*144 + c8*2), Aq + (size_t)(q0+m)*QKVq + c8);
    }
    CPA_COMMIT();
    #pragma unroll
    for (int p = 0; p < 4; p++) {
        int i = t + p * 512, m = i >> 3, c8 = (i & 7) * 8;
        cpa16(smP + (uint32_t)(m*144 + c8*2), Pk + (size_t)(j0+m)*Eq + c8);
    }
    CPA_COMMIT();
    #pragma unroll
    for (int p = 0; p < 2; p++) {
        int i = t + p * 512, m = i >> 3, c8 = (i & 7) * 8;
        cpa16(smK + (uint32_t)(m*144 + c8*2), Bk + (size_t)(k0+m)*QKVq + c8);
    }
    CPA_COMMIT();

    float acc[2][4][4];
    auto zero_acc = [&]() {
        #pragma unroll
        for (int mi = 0; mi < 2; mi++)
            #pragma unroll
            for (int ni = 0; ni < 4; ni++)
                #pragma unroll
                for (int e = 0; e < 4; e++) acc[mi][ni][e] = 0.f;
    };

    CPA_WAIT(1);
    __syncthreads();

    if (t < 256) {
        const float* vv = vbb + h*64;
        float s = 0.f;
        #pragma unroll 8
        for (int dd = 0; dd < 64; dd++) s += vv[dd] * __half2float(Ph[t*72 + dd]);
        Sd[t] = s * SCALEF;
    }
    __syncthreads();

    // ---- BD: two 128-col j-chunks, 4 k16 steps each ----
    #pragma unroll 1
    for (int jc = 0; jc < 2; jc++) {
        zero_acc();
        #pragma unroll
        for (int s = 0; s < 4; s++) {
            const int kb = s * 16;
            uint32_t af[2][4], bf[2][4];
            #pragma unroll
            for (int mi = 0; mi < 2; mi++)
                ldsm4(af[mi], smQ + ((wm + mi*16 + aRow)*72 + kb + aK)*2);
            #pragma unroll
            for (int nj = 0; nj < 2; nj++)
                ldsm4(bf[nj], smP + ((jc*128 + wn + nj*16 + bRow)*72 + kb + bK)*2);
            #pragma unroll
            for (int mi = 0; mi < 2; mi++)
                #pragma unroll
                for (int ni = 0; ni < 4; ni++)
                    mma_f16(acc[mi][ni], af[mi], &bf[ni >> 1][(ni & 1) * 2]);
        }
        #pragma unroll
        for (int mi = 0; mi < 2; mi++) {
            int row = wm + mi * 16 + g;
            #pragma unroll
            for (int ni = 0; ni < 4; ni++) {
                int col = wn + ni * 8 + 2 * q4;
                int jcol = jc * 128 + col;
                D[row*260 + jcol]       = __float2half(SCALEF*acc[mi][ni][0] + Sd[jcol]);
                D[row*260 + jcol+1]     = __float2half(SCALEF*acc[mi][ni][1] + Sd[jcol+1]);
                D[(row+8)*260 + jcol]   = __float2half(SCALEF*acc[mi][ni][2] + Sd[jcol]);
                D[(row+8)*260 + jcol+1] = __float2half(SCALEF*acc[mi][ni][3] + Sd[jcol+1]);
            }
        }
    }

    CPA_WAIT(0);
    __syncthreads();

    if (t < 128) {
        const float* uu = ub + h*64;
        float s = 0.f;
        #pragma unroll 8
        for (int dd = 0; dd < 64; dd++) s += uu[dd] * __half2float(Kh[t*72 + dd]);
        Sc[t] = s * SCALEF;
    }
    __syncthreads();

    // ---- AC ----
    zero_acc();
    #pragma unroll
    for (int s = 0; s < 4; s++) {
        const int kb = s * 16;
        uint32_t af[2][4], bf[2][4];
        #pragma unroll
        for (int mi = 0; mi < 2; mi++)
            ldsm4(af[mi], smQ + ((wm + mi*16 + aRow)*72 + kb + aK)*2);
        #pragma unroll
        for (int nj = 0; nj < 2; nj++)
            ldsm4(bf[nj], smK + ((wn + nj*16 + bRow)*72 + kb + bK)*2);
        #pragma unroll
        for (int mi = 0; mi < 2; mi++)
            #pragma unroll
            for (int ni = 0; ni < 4; ni++)
                mma_f16(acc[mi][ni], af[mi], &bf[ni >> 1][(ni & 1) * 2]);
    }

    // ---- combine ----
    #pragma unroll
    for (int mi = 0; mi < 2; mi++) {
        int row = wm + mi * 16 + g;
        #pragma unroll
        for (int ni = 0; ni < 4; ni++) {
            int c = wn + ni * 8 + 2 * q4;
            int jb = c - row + 127;
            float v0 = SCALEF*acc[mi][ni][0] + Sc[c]   + __half2float(D[row*260 + jb]);
            float v1 = SCALEF*acc[mi][ni][1] + Sc[c+1] + __half2float(D[row*260 + jb+1]);
            *(float2*)(Cc + (size_t)(q0+row)*Lq + k0 + c) = make_float2(v0, v1);
            int row2 = row + 8, jb2 = jb - 8;
            float v2 = SCALEF*acc[mi][ni][2] + Sc[c]   + __half2float(D[row2*260 + jb2]);
            float v3 = SCALEF*acc[mi][ni][3] + Sc[c+1] + __half2float(D[row2*260 + jb2+1]);
            *(float2*)(Cc + (size_t)(q0+row2)*Lq + k0 + c) = make_float2(v2, v3);
        }
    }
}

// ---------------------------------------------------------------------------
// Row softmax in-place (fp32).
// ---------------------------------------------------------------------------
__global__ void softmax_kernel(float* __restrict__ attn)
{
    float* row = attn + (size_t)blockIdx.x * Lq;
    const int t = threadIdx.x;
    float4 v = *(reinterpret_cast<float4*>(row) + t);

    float m = fmaxf(fmaxf(v.x, v.y), fmaxf(v.z, v.w));
    #pragma unroll
    for (int o = 16; o > 0; o >>= 1) m = fmaxf(m, __shfl_xor_sync(0xffffffffu, m, o));
    __shared__ float red[8];
    if ((t & 31) == 0) red[t >> 5] = m;
    __syncthreads();
    float bm = red[0];
    #pragma unroll
    for (int i = 1; i < 8; i++) bm = fmaxf(bm, red[i]);

    v.x = expf(v.x - bm); v.y = expf(v.y - bm);
    v.z = expf(v.z - bm); v.w = expf(v.w - bm);
    float s = v.x + v.y + v.z + v.w;
    #pragma unroll
    for (int o = 16; o > 0; o >>= 1) s += __shfl_xor_sync(0xffffffffu, s, o);
    __syncthreads();
    if ((t & 31) == 0) red[t >> 5] = s;
    __syncthreads();
    float bs = red[0];
    #pragma unroll
    for (int i = 1; i < 8; i++) bs += red[i];
    float inv = 1.0f / bs;
    v.x *= inv; v.y *= inv; v.z *= inv; v.w *= inv;
    *(reinterpret_cast<float4*>(row) + t) = v;
}

// ---------------------------------------------------------------------------
// ctx = attn @ V (fp16 mma + ldmatrix). A=attn fp32 (cvt), B=g_vt half [n][k].
// 128(M)x64(N) tile, BK=16, 256 threads (8 warps 4x2), warp 32x32.
// ---------------------------------------------------------------------------
__global__ void __launch_bounds__(256, 2)
ctx_h(const float* __restrict__ attn)
{
    const int z = blockIdx.z, b = z >> 3, h = z & 7;
    const float*  A  = attn + (size_t)z * Lq * Lq;
    const __half* Vt = g_vt + (size_t)z * 64 * Lq;   // [n][k]
    __half*       Cm = g_ctxh + (size_t)b*Lq*Eq + h*64;

    __shared__ uint32_t As[2][128 * GS];
    __shared__ uint32_t Bs[2][64 * GS];
    const int m0 = blockIdx.y * 128;
    const int t = threadIdx.x, lane = t & 31, warp = t >> 5;
    const int wm = (warp & 3) * 32, wn = (warp >> 2) * 32;
    const int g = lane >> 2, q4 = lane & 3;
    const int lr = t >> 1, kh = (t & 1) * 8;

    const int aRow = lane & 15, aK = (lane >> 4) << 3;
    const int bRow = (lane & 7) + ((lane >> 4) << 3), bK = ((lane >> 3) & 1) << 3;

    float acc[2][4][4] = {};
    float4 fa0, fa1;
    uint4  bv;

    auto ldg = [&](int k0) {
        fa0 = *(const float4*)(A + (size_t)(m0+lr)*Lq + k0 + kh);
        fa1 = *(const float4*)(A + (size_t)(m0+lr)*Lq + k0 + kh + 4);
        if (t < 128)
            bv = *(const uint4*)(Vt + (size_t)(t >> 1)*Lq + k0 + kh);
    };
    auto sts = [&](int buf) {
        int w = lr * GS + (kh >> 1);
        As[buf][w]   = h2u(fa0.x, fa0.y); As[buf][w+1] = h2u(fa0.z, fa0.w);
        As[buf][w+2] = h2u(fa1.x, fa1.y); As[buf][w+3] = h2u(fa1.z, fa1.w);
        if (t < 128) {
            int wb = (t >> 1) * GS + (kh >> 1);
            Bs[buf][wb]   = bv.x; Bs[buf][wb+1] = bv.y;
            Bs[buf][wb+2] = bv.z; Bs[buf][wb+3] = bv.w;
        }
    };

    ldg(0); sts(0);
    __syncthreads();

    for (int it = 0; it < 64; it++) {
        int buf = it & 1;
        if (it + 1 < 64) ldg((it + 1) * 16);
        uint32_t aSm = (uint32_t)__cvta_generic_to_shared(&As[buf][0]);
        uint32_t bSm = (uint32_t)__cvta_generic_to_shared(&Bs[buf][0]);
        uint32_t af[2][4], bf[2][4];
        #pragma unroll
        for (int mi = 0; mi < 2; mi++)
            ldsm4(af[mi], aSm + ((wm + mi*16 + aRow)*24 + aK)*2);
        #pragma unroll
        for (int nj = 0; nj < 2; nj++)
            ldsm4(bf[nj], bSm + ((wn + nj*16 + bRow)*24 + bK)*2);
        #pragma unroll
        for (int mi = 0; mi < 2; mi++)
            #pragma unroll
            for (int ni = 0; ni < 4; ni++)
                mma_f16(acc[mi][ni], af[mi], &bf[ni >> 1][(ni & 1) * 2]);
        if (it + 1 < 64) sts(buf ^ 1);
        __syncthreads();
    }

    #pragma unroll
    for (int mi = 0; mi < 2; mi++) {
        int row = m0 + wm + mi * 16 + g;
        #pragma unroll
        for (int ni = 0; ni < 4; ni++) {
            int col = wn + ni * 8 + 2 * q4;
            *(uint32_t*)(Cm + (size_t)row*Eq + col) =
                h2u(acc[mi][ni][0], acc[mi][ni][1]);
            *(uint32_t*)(Cm + (size_t)(row+8)*Eq + col) =
                h2u(acc[mi][ni][2], acc[mi][ni][3]);
        }
    }
}

// ---------------------------------------------------------------------------
// Out projection: out = ctxh @ W^T + bias. A half, W fp32 -> half, out fp32.
// ---------------------------------------------------------------------------
__global__ void __launch_bounds__(256, 2)
gemm_out(const __half* __restrict__ A, const float* __restrict__ W,
         const float* __restrict__ bias, float* __restrict__ C,
         int M, int N, int K)
{
    __shared__ uint32_t As[2][128 * GS];
    __shared__ uint32_t Bs[2][128 * GS];
    const int m0 = blockIdx.y * 128, n0 = blockIdx.x * 128;
    const int t = threadIdx.x, lane = t & 31, warp = t >> 5;
    const int wm = (warp & 1) * 64, wn = (warp >> 1) * 32;
    const int g = lane >> 2, q4 = lane & 3;
    const int lr = t >> 1, kh = (t & 1) * 8;

    const int aRow = lane & 15, aK = (lane >> 4) << 3;
    const int bRow = (lane & 7) + ((lane >> 4) << 3), bK = ((lane >> 3) & 1) << 3;

    float acc[4][4][4] = {};
    uint4 av;
    float4 fw0, fw1;

    auto ldg = [&](int k0) {
        av  = *(const uint4*)(A + (size_t)(m0+lr)*K + k0 + kh);
        fw0 = *(const float4*)(W + (size_t)(n0+lr)*K + k0 + kh);
        fw1 = *(const float4*)(W + (size_t)(n0+lr)*K + k0 + kh + 4);
    };
    auto sts = [&](int buf) {
        int w = lr * GS + (kh >> 1);
        As[buf][w]   = av.x; As[buf][w+1] = av.y;
        As[buf][w+2] = av.z; As[buf][w+3] = av.w;
        Bs[buf][w]   = h2u(fw0.x, fw0.y); Bs[buf][w+1] = h2u(fw0.z, fw0.w);
        Bs[buf][w+2] = h2u(fw1.x, fw1.y); Bs[buf][w+3] = h2u(fw1.z, fw1.w);
    };

    const int nIt = K / 16;
    ldg(0); sts(0);
    __syncthreads();

    for (int it = 0; it < nIt; it++) {
        int buf = it & 1;
        if (it + 1 < nIt) ldg((it + 1) * 16);
        uint32_t aSm = (uint32_t)__cvta_generic_to_shared(&As[buf][0]);
        uint32_t bSm = (uint32_t)__cvta_generic_to_shared(&Bs[buf][0]);
        uint32_t af[4][4], bf[2][4];
        #pragma unroll
        for (int mi = 0; mi < 4; mi++)
            ldsm4(af[mi], aSm + ((wm + mi*16 + aRow)*24 + aK)*2);
        #pragma unroll
        for (int nj = 0; nj < 2; nj++)
            ldsm4(bf[nj], bSm + ((wn + nj*16 + bRow)*24 + bK)*2);
        #pragma unroll
        for (int mi = 0; mi < 4; mi++)
            #pragma unroll
            for (int ni = 0; ni < 4; ni++)
                mma_f16(acc[mi][ni], af[mi], &bf[ni >> 1][(ni & 1) * 2]);
        if (it + 1 < nIt) sts(buf ^ 1);
        __syncthreads();
    }

    #pragma unroll
    for (int mi = 0; mi < 4; mi++) {
        int row = m0 + wm + mi * 16 + g;
        #pragma unroll
        for (int ni = 0; ni < 4; ni++) {
            int col = n0 + wn + ni * 8 + 2 * q4;
            float b0 = bias[col], b1 = bias[col+1];
            *(float2*)(C + (size_t)row*N + col) =
                make_float2(acc[mi][ni][0] + b0, acc[mi][ni][1] + b1);
            *(float2*)(C + (size_t)(row+8)*N + col) =
                make_float2(acc[mi][ni][2] + b0, acc[mi][ni][3] + b1);
        }
    }
}

// ---------------------------------------------------------------------------
extern "C" void kernel_launch(void* const* d_in, const int* in_sizes, int n_in,
                              void* d_out, int out_size)
{
    const float* x     = (const float*)d_in[0];
    const float* pos   = (const float*)d_in[1];
    const float* w_in  = (const float*)d_in[2];
    const float* w_pos = (const float*)d_in[3];
    const float* w_out = (const float*)d_in[4];
    const float* b_out = (const float*)d_in[5];
    const float* ub    = (const float*)d_in[6];
    const float* vbb   = (const float*)d_in[7];
    float* out = (float*)d_out;

    __half *projh, *pkh, *ctxh;
    float *attn_fb;
    cudaGetSymbolAddress((void**)&projh,   g_projh);
    cudaGetSymbolAddress((void**)&pkh,     g_pkh);
    cudaGetSymbolAddress((void**)&ctxh,    g_ctxh);
    cudaGetSymbolAddress((void**)&attn_fb, g_attn_fb);

    cudaFuncSetAttribute(score_h, cudaFuncAttributeMaxDynamicSharedMemorySize,
                         SCORE_SMEM);

    const size_t OUT_E  = (size_t)BLq * Eq;
    const size_t ATTN_E = (size_t)Bq * Hq * Lq * Lq;
    float* attn = ((size_t)out_size >= OUT_E + ATTN_E) ? (out + OUT_E) : attn_fb;

    // 1) QKV projection -> fp16
    gemm_h<<<dim3(QKVq/128, BLq/128), 256>>>(x, w_in, projh,
                                             BLq, QKVq, Eq, Eq, Eq, QKVq);
    // 2) positional keys -> fp16
    gemm_h<<<dim3(Eq/128, (Pq+127)/128), 256>>>(pos, w_pos, pkh,
                                                Pq, Eq, Eq, Eq, Eq, Eq);
    // 3) V transpose for ctx B operand
    vtrans<<<dim3(Lq/64, Bq*Hq), 128>>>();
    // 4) fused AC + shifted BD logits (fp16 mma + ldmatrix)
    score_h<<<dim3(Lq/128, Lq/128, Bq*Hq), 512, SCORE_SMEM>>>(ub, vbb, attn);
    // 5) softmax (fp32)
    softmax_kernel<<<Bq*Hq*Lq, 256>>>(attn);
    // 6) ctx = attn @ V (fp16 mma + ldmatrix) -> fp16
    ctx_h<<<dim3(1, Lq/128, Bq*Hq), 256>>>(attn);
    // 7) out projection + bias
    gemm_out<<<dim3(Eq/128, BLq/128), 256>>>(ctxh, w_out, b_out, out,
                                             BLq, Eq, Eq);
}

// round 15
// speedup vs baseline: 1.8079x; 1.1480x over previous
#include <cuda_runtime.h>
#include <cuda_bf16.h>
#include <cuda_fp16.h>
#include <cstdint>
#include <math.h>

#define Bq   8
#define Lq   1024
#define Eq   512
#define Hq   8
#define HDq  64
#define Pq   2047
#define BLq  8192
#define QKVq 1536
#define SCALEF 0.044194173824159216f  // 1/sqrt(512)

__device__ __half g_projh[(size_t)BLq * QKVq];
__device__ __half g_pkh[(size_t)(Pq + 1) * Eq];
__device__ __half g_vt[(size_t)Bq * Hq * HDq * Lq];
__device__ __half g_ctxh[(size_t)BLq * Eq];
__device__ float  g_attn_fb[(size_t)Bq * Hq * Lq * Lq];

// score smem: Q[128][72]h + K[128][72]h + P[256][72]h + ACs[128][132]h + Sc/Sd
#define SCORE_SMEM ((128*72 + 128*72 + 256*72)*2 + 128*132*2 + 128*4 + 256*4) // 109056

__device__ __forceinline__ void mma_f16(float c[4], const uint32_t a[4],
                                        const uint32_t b[2]) {
    asm volatile(
        "mma.sync.aligned.m16n8k16.row.col.f32.f16.f16.f32 "
        "{%0,%1,%2,%3}, {%4,%5,%6,%7}, {%8,%9}, {%0,%1,%2,%3};"
        : "+f"(c[0]), "+f"(c[1]), "+f"(c[2]), "+f"(c[3])
        : "r"(a[0]), "r"(a[1]), "r"(a[2]), "r"(a[3]), "r"(b[0]), "r"(b[1]));
}

__device__ __forceinline__ void ldsm4(uint32_t r[4], uint32_t addr) {
    asm volatile("ldmatrix.sync.aligned.m8n8.x4.shared.b16 {%0,%1,%2,%3}, [%4];"
                 : "=r"(r[0]), "=r"(r[1]), "=r"(r[2]), "=r"(r[3]) : "r"(addr));
}

__device__ __forceinline__ uint32_t h2u(float x, float y) {
    __half2 h = __floats2half2_rn(x, y);
    return *(uint32_t*)&h;
}

__device__ __forceinline__ void cpa16(uint32_t dst_smem, const void* src) {
    asm volatile("cp.async.cg.shared.global [%0], [%1], 16;"
                 :: "r"(dst_smem), "l"(src));
}
#define CPA_COMMIT() asm volatile("cp.async.commit_group;")
#define CPA_WAIT(n)  asm volatile("cp.async.wait_group %0;" :: "n"(n))

#define GS 12

// ---------------------------------------------------------------------------
// FP16 GEMM (fp32 inputs): C[M,N] = A @ W^T, C stored as HALF.
// ---------------------------------------------------------------------------
__global__ void __launch_bounds__(256, 2)
gemm_h(const float* __restrict__ A, const float* __restrict__ W,
       __half* __restrict__ C, int M, int N, int K, int lda, int ldw, int ldc)
{
    __shared__ uint32_t As[2][128 * GS];
    __shared__ uint32_t Bs[2][128 * GS];
    const int m0 = blockIdx.y * 128, n0 = blockIdx.x * 128;
    const int t = threadIdx.x, lane = t & 31, warp = t >> 5;
    const int wm = (warp & 1) * 64, wn = (warp >> 1) * 32;
    const int g = lane >> 2, q4 = lane & 3;
    const int lr = t >> 1, kh = (t & 1) * 8;

    const int aRow = lane & 15, aK = (lane >> 4) << 3;
    const int bRow = (lane & 7) + ((lane >> 4) << 3), bK = ((lane >> 3) & 1) << 3;

    float acc[4][4][4] = {};
    float4 fa0, fa1, fw0, fw1;

    auto ldg = [&](int k0) {
        fa0 = make_float4(0,0,0,0); fa1 = make_float4(0,0,0,0);
        fw0 = make_float4(0,0,0,0); fw1 = make_float4(0,0,0,0);
        if (m0 + lr < M) {
            fa0 = *(const float4*)(A + (size_t)(m0+lr)*lda + k0 + kh);
            fa1 = *(const float4*)(A + (size_t)(m0+lr)*lda + k0 + kh + 4);
        }
        if (n0 + lr < N) {
            fw0 = *(const float4*)(W + (size_t)(n0+lr)*ldw + k0 + kh);
            fw1 = *(const float4*)(W + (size_t)(n0+lr)*ldw + k0 + kh + 4);
        }
    };
    auto sts = [&](int buf) {
        int w = lr * GS + (kh >> 1);
        As[buf][w]   = h2u(fa0.x, fa0.y); As[buf][w+1] = h2u(fa0.z, fa0.w);
        As[buf][w+2] = h2u(fa1.x, fa1.y); As[buf][w+3] = h2u(fa1.z, fa1.w);
        Bs[buf][w]   = h2u(fw0.x, fw0.y); Bs[buf][w+1] = h2u(fw0.z, fw0.w);
        Bs[buf][w+2] = h2u(fw1.x, fw1.y); Bs[buf][w+3] = h2u(fw1.z, fw1.w);
    };

    const int nIt = K / 16;
    ldg(0); sts(0);
    __syncthreads();

    for (int it = 0; it < nIt; it++) {
        int buf = it & 1;
        if (it + 1 < nIt) ldg((it + 1) * 16);
        uint32_t aSm = (uint32_t)__cvta_generic_to_shared(&As[buf][0]);
        uint32_t bSm = (uint32_t)__cvta_generic_to_shared(&Bs[buf][0]);
        uint32_t af[4][4], bf[2][4];
        #pragma unroll
        for (int mi = 0; mi < 4; mi++)
            ldsm4(af[mi], aSm + ((wm + mi*16 + aRow)*24 + aK)*2);
        #pragma unroll
        for (int nj = 0; nj < 2; nj++)
            ldsm4(bf[nj], bSm + ((wn + nj*16 + bRow)*24 + bK)*2);
        #pragma unroll
        for (int mi = 0; mi < 4; mi++)
            #pragma unroll
            for (int ni = 0; ni < 4; ni++)
                mma_f16(acc[mi][ni], af[mi], &bf[ni >> 1][(ni & 1) * 2]);
        if (it + 1 < nIt) sts(buf ^ 1);
        __syncthreads();
    }

    #pragma unroll
    for (int mi = 0; mi < 4; mi++) {
        int row = m0 + wm + mi * 16 + g;
        #pragma unroll
        for (int ni = 0; ni < 4; ni++) {
            int col = n0 + wn + ni * 8 + 2 * q4;
            if (row < M)
                *(uint32_t*)(C + (size_t)row*ldc + col) =
                    h2u(acc[mi][ni][0], acc[mi][ni][1]);
            if (row + 8 < M)
                *(uint32_t*)(C + (size_t)(row+8)*ldc + col) =
                    h2u(acc[mi][ni][2], acc[mi][ni][3]);
        }
    }
}

// ---------------------------------------------------------------------------
// V transpose: g_projh v-part [l][n] -> g_vt [z][n][l].
// ---------------------------------------------------------------------------
__global__ void vtrans()
{
    __shared__ __half T[64][72];
    const int z = blockIdx.y, b = z >> 3, h = z & 7;
    const int l0 = blockIdx.x * 64;
    const int t = threadIdx.x;
    const __half* src = g_projh + (size_t)(b * Lq) * QKVq + h*192 + 128;

    for (int i = t; i < 512; i += 128) {
        int row = i >> 3, ch = i & 7;
        uint4 v = *(const uint4*)(src + (size_t)(l0+row)*QKVq + ch*8);
        const __half* hv = (const __half*)&v;
        #pragma unroll
        for (int j = 0; j < 8; j++) T[ch*8 + j][row] = hv[j];
    }
    __syncthreads();
    for (int i = t; i < 512; i += 128) {
        int n = i >> 3, ch = i & 7;
        uint4 v; __half* hv = (__half*)&v;
        #pragma unroll
        for (int j = 0; j < 8; j++) hv[j] = T[n][ch*8 + j];
        *(uint4*)(g_vt + ((size_t)z*64 + n)*Lq + l0 + ch*8) = v;
    }
}

// ---------------------------------------------------------------------------
// Score kernel v5: AC-first into fp16 smem tile, BD RMW with diagonal shift,
// coalesced final store. smem 109KB -> 2 CTAs/SM.
// 512 threads (16 warps 4x4), warp tile 32x32.
// ---------------------------------------------------------------------------
__global__ void __launch_bounds__(512, 2)
score_h(const float* __restrict__ ub, const float* __restrict__ vbb,
        float* __restrict__ attn)
{
    extern __shared__ char sm_raw[];
    __half* Qh  = (__half*)sm_raw;                // [128][72]
    __half* Kh  = Qh + 128*72;                    // [128][72]
    __half* Ph  = Kh + 128*72;                    // [256][72]
    __half* ACs = Ph + 256*72;                    // [128][132]
    float*  Sc  = (float*)(ACs + 128*132);        // [128]
    float*  Sd  = Sc + 128;                       // [256]

    const int z = blockIdx.z, b = z >> 3, h = z & 7;
    const int q0 = blockIdx.y * 128, k0 = blockIdx.x * 128;
    const __half* Aq = g_projh + (size_t)b*Lq*QKVq + h*192;
    const __half* Bk = Aq + 64;
    const __half* Pk = g_pkh + h*64;
    float* Cc = attn + (size_t)z * Lq * Lq;
    const int j0 = k0 - q0 + 896;

    const int t = threadIdx.x, lane = t & 31, warp = t >> 5;
    const int wm = (warp & 3) * 32, wn = (warp >> 2) * 32;
    const int g = lane >> 2, q4 = lane & 3;

    const int aRow = lane & 15, aK = (lane >> 4) << 3;
    const int bRow = (lane & 7) + ((lane >> 4) << 3), bK = ((lane >> 3) & 1) << 3;

    const uint32_t smQ = (uint32_t)__cvta_generic_to_shared(Qh);
    const uint32_t smK = (uint32_t)__cvta_generic_to_shared(Kh);
    const uint32_t smP = (uint32_t)__cvta_generic_to_shared(Ph);

    // group A: Q + K ; group B: P
    #pragma unroll
    for (int p = 0; p < 2; p++) {
        int i = t + p * 512, m = i >> 3, c8 = (i & 7) * 8;
        cpa16(smQ + (uint32_t)(m*144 + c8*2), Aq + (size_t)(q0+m)*QKVq + c8);
    }
    #pragma unroll
    for (int p = 0; p < 2; p++) {
        int i = t + p * 512, m = i >> 3, c8 = (i & 7) * 8;
        cpa16(smK + (uint32_t)(m*144 + c8*2), Bk + (size_t)(k0+m)*QKVq + c8);
    }
    CPA_COMMIT();
    #pragma unroll
    for (int p = 0; p < 4; p++) {
        int i = t + p * 512, m = i >> 3, c8 = (i & 7) * 8;
        cpa16(smP + (uint32_t)(m*144 + c8*2), Pk + (size_t)(j0+m)*Eq + c8);
    }
    CPA_COMMIT();

    float acc[2][4][4];
    auto zero_acc = [&]() {
        #pragma unroll
        for (int mi = 0; mi < 2; mi++)
            #pragma unroll
            for (int ni = 0; ni < 4; ni++)
                #pragma unroll
                for (int e = 0; e < 4; e++) acc[mi][ni][e] = 0.f;
    };

    CPA_WAIT(1);               // Q, K ready
    __syncthreads();

    // c[k] = s * (u . K_k)
    if (t < 128) {
        const float* uu = ub + h*64;
        float s = 0.f;
        #pragma unroll 8
        for (int dd = 0; dd < 64; dd++) s += uu[dd] * __half2float(Kh[t*72 + dd]);
        Sc[t] = s * SCALEF;
    }

    // ---- AC mma ----
    zero_acc();
    #pragma unroll
    for (int s = 0; s < 4; s++) {
        const int kb = s * 16;
        uint32_t af[2][4], bf[2][4];
        #pragma unroll
        for (int mi = 0; mi < 2; mi++)
            ldsm4(af[mi], smQ + ((wm + mi*16 + aRow)*72 + kb + aK)*2);
        #pragma unroll
        for (int nj = 0; nj < 2; nj++)
            ldsm4(bf[nj], smK + ((wn + nj*16 + bRow)*72 + kb + bK)*2);
        #pragma unroll
        for (int mi = 0; mi < 2; mi++)
            #pragma unroll
            for (int ni = 0; ni < 4; ni++)
                mma_f16(acc[mi][ni], af[mi], &bf[ni >> 1][(ni & 1) * 2]);
    }
    __syncthreads();           // Sc visible; ACs writes ordered after

    // AC epilogue -> ACs fp16
    #pragma unroll
    for (int mi = 0; mi < 2; mi++) {
        int row = wm + mi * 16 + g;
        #pragma unroll
        for (int ni = 0; ni < 4; ni++) {
            int c = wn + ni * 8 + 2 * q4;
            *(uint32_t*)&ACs[row*132 + c] =
                h2u(SCALEF*acc[mi][ni][0] + Sc[c], SCALEF*acc[mi][ni][1] + Sc[c+1]);
            *(uint32_t*)&ACs[(row+8)*132 + c] =
                h2u(SCALEF*acc[mi][ni][2] + Sc[c], SCALEF*acc[mi][ni][3] + Sc[c+1]);
        }
    }

    CPA_WAIT(0);               // P ready
    __syncthreads();           // ACs writes visible to all

    // d[j] = s * (v . P_j)
    if (t < 256) {
        const float* vv = vbb + h*64;
        float s = 0.f;
        #pragma unroll 8
        for (int dd = 0; dd < 64; dd++) s += vv[dd] * __half2float(Ph[t*72 + dd]);
        Sd[t] = s * SCALEF;
    }
    __syncthreads();

    // ---- BD: two 128-col j-chunks, RMW into ACs with diagonal shift ----
    auto rmw = [&](int row, int c, float add) {
        if ((unsigned)c < 128u) {
            __half* p = &ACs[row*132 + c];
            *p = __float2half(__half2float(*p) + add);
        }
    };
    #pragma unroll 1
    for (int jc = 0; jc < 2; jc++) {
        zero_acc();
        #pragma unroll
        for (int s = 0; s < 4; s++) {
            const int kb = s * 16;
            uint32_t af[2][4], bf[2][4];
            #pragma unroll
            for (int mi = 0; mi < 2; mi++)
                ldsm4(af[mi], smQ + ((wm + mi*16 + aRow)*72 + kb + aK)*2);
            #pragma unroll
            for (int nj = 0; nj < 2; nj++)
                ldsm4(bf[nj], smP + ((jc*128 + wn + nj*16 + bRow)*72 + kb + bK)*2);
            #pragma unroll
            for (int mi = 0; mi < 2; mi++)
                #pragma unroll
                for (int ni = 0; ni < 4; ni++)
                    mma_f16(acc[mi][ni], af[mi], &bf[ni >> 1][(ni & 1) * 2]);
        }
        #pragma unroll
        for (int mi = 0; mi < 2; mi++) {
            int row = wm + mi * 16 + g;
            #pragma unroll
            for (int ni = 0; ni < 4; ni++) {
                int jcol = jc * 128 + wn + ni * 8 + 2 * q4;
                float d0 = Sd[jcol], d1 = Sd[jcol + 1];
                rmw(row, jcol + row - 127,     SCALEF*acc[mi][ni][0] + d0);
                rmw(row, jcol + 1 + row - 127, SCALEF*acc[mi][ni][1] + d1);
                int row2 = row + 8;
                rmw(row2, jcol + row2 - 127,     SCALEF*acc[mi][ni][2] + d0);
                rmw(row2, jcol + 1 + row2 - 127, SCALEF*acc[mi][ni][3] + d1);
            }
        }
    }
    __syncthreads();

    // ---- final coalesced store: ACs -> attn (fp32) ----
    for (int i = t; i < 128 * 32; i += 512) {
        int row = i >> 5, c4 = (i & 31) * 4;
        __half2 p0 = *(__half2*)&ACs[row*132 + c4];
        __half2 p1 = *(__half2*)&ACs[row*132 + c4 + 2];
        float2 f0 = __half22float2(p0), f1 = __half22float2(p1);
        *(float4*)(Cc + (size_t)(q0+row)*Lq + k0 + c4) =
            make_float4(f0.x, f0.y, f1.x, f1.y);
    }
}

// ---------------------------------------------------------------------------
// Row softmax in-place (fp32).
// ---------------------------------------------------------------------------
__global__ void softmax_kernel(float* __restrict__ attn)
{
    float* row = attn + (size_t)blockIdx.x * Lq;
    const int t = threadIdx.x;
    float4 v = *(reinterpret_cast<float4*>(row) + t);

    float m = fmaxf(fmaxf(v.x, v.y), fmaxf(v.z, v.w));
    #pragma unroll
    for (int o = 16; o > 0; o >>= 1) m = fmaxf(m, __shfl_xor_sync(0xffffffffu, m, o));
    __shared__ float red[8];
    if ((t & 31) == 0) red[t >> 5] = m;
    __syncthreads();
    float bm = red[0];
    #pragma unroll
    for (int i = 1; i < 8; i++) bm = fmaxf(bm, red[i]);

    v.x = expf(v.x - bm); v.y = expf(v.y - bm);
    v.z = expf(v.z - bm); v.w = expf(v.w - bm);
    float s = v.x + v.y + v.z + v.w;
    #pragma unroll
    for (int o = 16; o > 0; o >>= 1) s += __shfl_xor_sync(0xffffffffu, s, o);
    __syncthreads();
    if ((t & 31) == 0) red[t >> 5] = s;
    __syncthreads();
    float bs = red[0];
    #pragma unroll
    for (int i = 1; i < 8; i++) bs += red[i];
    float inv = 1.0f / bs;
    v.x *= inv; v.y *= inv; v.z *= inv; v.w *= inv;
    *(reinterpret_cast<float4*>(row) + t) = v;
}

// ---------------------------------------------------------------------------
// ctx = attn @ V (fp16 mma + ldmatrix). B=g_vt half [n][k].
// ---------------------------------------------------------------------------
__global__ void __launch_bounds__(256, 2)
ctx_h(const float* __restrict__ attn)
{
    const int z = blockIdx.z, b = z >> 3, h = z & 7;
    const float*  A  = attn + (size_t)z * Lq * Lq;
    const __half* Vt = g_vt + (size_t)z * 64 * Lq;
    __half*       Cm = g_ctxh + (size_t)b*Lq*Eq + h*64;

    __shared__ uint32_t As[2][128 * GS];
    __shared__ uint32_t Bs[2][64 * GS];
    const int m0 = blockIdx.y * 128;
    const int t = threadIdx.x, lane = t & 31, warp = t >> 5;
    const int wm = (warp & 3) * 32, wn = (warp >> 2) * 32;
    const int g = lane >> 2, q4 = lane & 3;
    const int lr = t >> 1, kh = (t & 1) * 8;

    const int aRow = lane & 15, aK = (lane >> 4) << 3;
    const int bRow = (lane & 7) + ((lane >> 4) << 3), bK = ((lane >> 3) & 1) << 3;

    float acc[2][4][4] = {};
    float4 fa0, fa1;
    uint4  bv;

    auto ldg = [&](int k0) {
        fa0 = *(const float4*)(A + (size_t)(m0+lr)*Lq + k0 + kh);
        fa1 = *(const float4*)(A + (size_t)(m0+lr)*Lq + k0 + kh + 4);
        if (t < 128)
            bv = *(const uint4*)(Vt + (size_t)(t >> 1)*Lq + k0 + kh);
    };
    auto sts = [&](int buf) {
        int w = lr * GS + (kh >> 1);
        As[buf][w]   = h2u(fa0.x, fa0.y); As[buf][w+1] = h2u(fa0.z, fa0.w);
        As[buf][w+2] = h2u(fa1.x, fa1.y); As[buf][w+3] = h2u(fa1.z, fa1.w);
        if (t < 128) {
            int wb = (t >> 1) * GS + (kh >> 1);
            Bs[buf][wb]   = bv.x; Bs[buf][wb+1] = bv.y;
            Bs[buf][wb+2] = bv.z; Bs[buf][wb+3] = bv.w;
        }
    };

    ldg(0); sts(0);
    __syncthreads();

    for (int it = 0; it < 64; it++) {
        int buf = it & 1;
        if (it + 1 < 64) ldg((it + 1) * 16);
        uint32_t aSm = (uint32_t)__cvta_generic_to_shared(&As[buf][0]);
        uint32_t bSm = (uint32_t)__cvta_generic_to_shared(&Bs[buf][0]);
        uint32_t af[2][4], bf[2][4];
        #pragma unroll
        for (int mi = 0; mi < 2; mi++)
            ldsm4(af[mi], aSm + ((wm + mi*16 + aRow)*24 + aK)*2);
        #pragma unroll
        for (int nj = 0; nj < 2; nj++)
            ldsm4(bf[nj], bSm + ((wn + nj*16 + bRow)*24 + bK)*2);
        #pragma unroll
        for (int mi = 0; mi < 2; mi++)
            #pragma unroll
            for (int ni = 0; ni < 4; ni++)
                mma_f16(acc[mi][ni], af[mi], &bf[ni >> 1][(ni & 1) * 2]);
        if (it + 1 < 64) sts(buf ^ 1);
        __syncthreads();
    }

    #pragma unroll
    for (int mi = 0; mi < 2; mi++) {
        int row = m0 + wm + mi * 16 + g;
        #pragma unroll
        for (int ni = 0; ni < 4; ni++) {
            int col = wn + ni * 8 + 2 * q4;
            *(uint32_t*)(Cm + (size_t)row*Eq + col) =
                h2u(acc[mi][ni][0], acc[mi][ni][1]);
            *(uint32_t*)(Cm + (size_t)(row+8)*Eq + col) =
                h2u(acc[mi][ni][2], acc[mi][ni][3]);
        }
    }
}

// ---------------------------------------------------------------------------
// Out projection: out = ctxh @ W^T + bias.
// ---------------------------------------------------------------------------
__global__ void __launch_bounds__(256, 2)
gemm_out(const __half* __restrict__ A, const float* __restrict__ W,
         const float* __restrict__ bias, float* __restrict__ C,
         int M, int N, int K)
{
    __shared__ uint32_t As[2][128 * GS];
    __shared__ uint32_t Bs[2][128 * GS];
    const int m0 = blockIdx.y * 128, n0 = blockIdx.x * 128;
    const int t = threadIdx.x, lane = t & 31, warp = t >> 5;
    const int wm = (warp & 1) * 64, wn = (warp >> 1) * 32;
    const int g = lane >> 2, q4 = lane & 3;
    const int lr = t >> 1, kh = (t & 1) * 8;

    const int aRow = lane & 15, aK = (lane >> 4) << 3;
    const int bRow = (lane & 7) + ((lane >> 4) << 3), bK = ((lane >> 3) & 1) << 3;

    float acc[4][4][4] = {};
    uint4 av;
    float4 fw0, fw1;

    auto ldg = [&](int k0) {
        av  = *(const uint4*)(A + (size_t)(m0+lr)*K + k0 + kh);
        fw0 = *(const float4*)(W + (size_t)(n0+lr)*K + k0 + kh);
        fw1 = *(const float4*)(W + (size_t)(n0+lr)*K + k0 + kh + 4);
    };
    auto sts = [&](int buf) {
        int w = lr * GS + (kh >> 1);
        As[buf][w]   = av.x; As[buf][w+1] = av.y;
        As[buf][w+2] = av.z; As[buf][w+3] = av.w;
        Bs[buf][w]   = h2u(fw0.x, fw0.y); Bs[buf][w+1] = h2u(fw0.z, fw0.w);
        Bs[buf][w+2] = h2u(fw1.x, fw1.y); Bs[buf][w+3] = h2u(fw1.z, fw1.w);
    };

    const int nIt = K / 16;
    ldg(0); sts(0);
    __syncthreads();

    for (int it = 0; it < nIt; it++) {
        int buf = it & 1;
        if (it + 1 < nIt) ldg((it + 1) * 16);
        uint32_t aSm = (uint32_t)__cvta_generic_to_shared(&As[buf][0]);
        uint32_t bSm = (uint32_t)__cvta_generic_to_shared(&Bs[buf][0]);
        uint32_t af[4][4], bf[2][4];
        #pragma unroll
        for (int mi = 0; mi < 4; mi++)
            ldsm4(af[mi], aSm + ((wm + mi*16 + aRow)*24 + aK)*2);
        #pragma unroll
        for (int nj = 0; nj < 2; nj++)
            ldsm4(bf[nj], bSm + ((wn + nj*16 + bRow)*24 + bK)*2);
        #pragma unroll
        for (int mi = 0; mi < 4; mi++)
            #pragma unroll
            for (int ni = 0; ni < 4; ni++)
                mma_f16(acc[mi][ni], af[mi], &bf[ni >> 1][(ni & 1) * 2]);
        if (it + 1 < nIt) sts(buf ^ 1);
        __syncthreads();
    }

    #pragma unroll
    for (int mi = 0; mi < 4; mi++) {
        int row = m0 + wm + mi * 16 + g;
        #pragma unroll
        for (int ni = 0; ni < 4; ni++) {
            int col = n0 + wn + ni * 8 + 2 * q4;
            float b0 = bias[col], b1 = bias[col+1];
            *(float2*)(C + (size_t)row*N + col) =
                make_float2(acc[mi][ni][0] + b0, acc[mi][ni][1] + b1);
            *(float2*)(C + (size_t)(row+8)*N + col) =
                make_float2(acc[mi][ni][2] + b0, acc[mi][ni][3] + b1);
        }
    }
}

// ---------------------------------------------------------------------------
extern "C" void kernel_launch(void* const* d_in, const int* in_sizes, int n_in,
                              void* d_out, int out_size)
{
    const float* x     = (const float*)d_in[0];
    const float* pos   = (const float*)d_in[1];
    const float* w_in  = (const float*)d_in[2];
    const float* w_pos = (const float*)d_in[3];
    const float* w_out = (const float*)d_in[4];
    const float* b_out = (const float*)d_in[5];
    const float* ub    = (const float*)d_in[6];
    const float* vbb   = (const float*)d_in[7];
    float* out = (float*)d_out;

    __half *projh, *pkh, *ctxh;
    float *attn_fb;
    cudaGetSymbolAddress((void**)&projh,   g_projh);
    cudaGetSymbolAddress((void**)&pkh,     g_pkh);
    cudaGetSymbolAddress((void**)&ctxh,    g_ctxh);
    cudaGetSymbolAddress((void**)&attn_fb, g_attn_fb);

    cudaFuncSetAttribute(score_h, cudaFuncAttributeMaxDynamicSharedMemorySize,
                         SCORE_SMEM);

    const size_t OUT_E  = (size_t)BLq * Eq;
    const size_t ATTN_E = (size_t)Bq * Hq * Lq * Lq;
    float* attn = ((size_t)out_size >= OUT_E + ATTN_E) ? (out + OUT_E) : attn_fb;

    // 1) QKV projection -> fp16
    gemm_h<<<dim3(QKVq/128, BLq/128), 256>>>(x, w_in, projh,
                                             BLq, QKVq, Eq, Eq, Eq, QKVq);
    // 2) positional keys -> fp16
    gemm_h<<<dim3(Eq/128, (Pq+127)/128), 256>>>(pos, w_pos, pkh,
                                                Pq, Eq, Eq, Eq, Eq, Eq);
    // 3) V transpose
    vtrans<<<dim3(Lq/64, Bq*Hq), 128>>>();
    // 4) fused AC + shifted BD logits (AC-first, smem RMW, 2 CTAs/SM)
    score_h<<<dim3(Lq/128, Lq/128, Bq*Hq), 512, SCORE_SMEM>>>(ub, vbb, attn);
    // 5) softmax
    softmax_kernel<<<Bq*Hq*Lq, 256>>>(attn);
    // 6) ctx = attn @ V -> fp16
    ctx_h<<<dim3(1, Lq/128, Bq*Hq), 256>>>(attn);
    // 7) out projection + bias
    gemm_out<<<dim3(Eq/128, BLq/128), 256>>>(ctxh, w_out, b_out, out,
                                             BLq, Eq, Eq);
}

// round 16
// speedup vs baseline: 2.0250x; 1.1201x over previous
#include <cuda_runtime.h>
#include <cuda_bf16.h>
#include <cuda_fp16.h>
#include <cstdint>
#include <math.h>

#define Bq   8
#define Lq   1024
#define Eq   512
#define Hq   8
#define HDq  64
#define Pq   2047
#define BLq  8192
#define QKVq 1536
#define SCALEF 0.044194173824159216f  // 1/sqrt(512)

__device__ __half g_projh[(size_t)BLq * QKVq];
__device__ __half g_pkh[(size_t)(Pq + 1) * Eq];
__device__ __half g_vt[(size_t)Bq * Hq * HDq * Lq];
__device__ __half g_ctxh[(size_t)BLq * Eq];
__device__ __half g_logith[(size_t)Bq * Hq * Lq * Lq];   // fp16 logits/probs
__device__ float  g_attn_fb[(size_t)Bq * Hq * Lq * Lq];

// score smem: Q[128][72]h + K[128][72]h + P[256][72]h + ACs[128][136]h + Sc/Sd
#define SCORE_SMEM ((128*72 + 128*72 + 256*72)*2 + 128*136*2 + 128*4 + 256*4) // 110080

__device__ __forceinline__ void mma_f16(float c[4], const uint32_t a[4],
                                        const uint32_t b[2]) {
    asm volatile(
        "mma.sync.aligned.m16n8k16.row.col.f32.f16.f16.f32 "
        "{%0,%1,%2,%3}, {%4,%5,%6,%7}, {%8,%9}, {%0,%1,%2,%3};"
        : "+f"(c[0]), "+f"(c[1]), "+f"(c[2]), "+f"(c[3])
        : "r"(a[0]), "r"(a[1]), "r"(a[2]), "r"(a[3]), "r"(b[0]), "r"(b[1]));
}

__device__ __forceinline__ void ldsm4(uint32_t r[4], uint32_t addr) {
    asm volatile("ldmatrix.sync.aligned.m8n8.x4.shared.b16 {%0,%1,%2,%3}, [%4];"
                 : "=r"(r[0]), "=r"(r[1]), "=r"(r[2]), "=r"(r[3]) : "r"(addr));
}

__device__ __forceinline__ uint32_t h2u(float x, float y) {
    __half2 h = __floats2half2_rn(x, y);
    return *(uint32_t*)&h;
}

__device__ __forceinline__ void cpa16(uint32_t dst_smem, const void* src) {
    asm volatile("cp.async.cg.shared.global [%0], [%1], 16;"
                 :: "r"(dst_smem), "l"(src));
}
#define CPA_COMMIT() asm volatile("cp.async.commit_group;")
#define CPA_WAIT(n)  asm volatile("cp.async.wait_group %0;" :: "n"(n))

#define GS 12

// ---------------------------------------------------------------------------
// FP16 GEMM (fp32 inputs): C[M,N] = A @ W^T, C stored as HALF.
// ---------------------------------------------------------------------------
__global__ void __launch_bounds__(256, 2)
gemm_h(const float* __restrict__ A, const float* __restrict__ W,
       __half* __restrict__ C, int M, int N, int K, int lda, int ldw, int ldc)
{
    __shared__ uint32_t As[2][128 * GS];
    __shared__ uint32_t Bs[2][128 * GS];
    const int m0 = blockIdx.y * 128, n0 = blockIdx.x * 128;
    const int t = threadIdx.x, lane = t & 31, warp = t >> 5;
    const int wm = (warp & 1) * 64, wn = (warp >> 1) * 32;
    const int g = lane >> 2, q4 = lane & 3;
    const int lr = t >> 1, kh = (t & 1) * 8;

    const int aRow = lane & 15, aK = (lane >> 4) << 3;
    const int bRow = (lane & 7) + ((lane >> 4) << 3), bK = ((lane >> 3) & 1) << 3;

    float acc[4][4][4] = {};
    float4 fa0, fa1, fw0, fw1;

    auto ldg = [&](int k0) {
        fa0 = make_float4(0,0,0,0); fa1 = make_float4(0,0,0,0);
        fw0 = make_float4(0,0,0,0); fw1 = make_float4(0,0,0,0);
        if (m0 + lr < M) {
            fa0 = *(const float4*)(A + (size_t)(m0+lr)*lda + k0 + kh);
            fa1 = *(const float4*)(A + (size_t)(m0+lr)*lda + k0 + kh + 4);
        }
        if (n0 + lr < N) {
            fw0 = *(const float4*)(W + (size_t)(n0+lr)*ldw + k0 + kh);
            fw1 = *(const float4*)(W + (size_t)(n0+lr)*ldw + k0 + kh + 4);
        }
    };
    auto sts = [&](int buf) {
        int w = lr * GS + (kh >> 1);
        As[buf][w]   = h2u(fa0.x, fa0.y); As[buf][w+1] = h2u(fa0.z, fa0.w);
        As[buf][w+2] = h2u(fa1.x, fa1.y); As[buf][w+3] = h2u(fa1.z, fa1.w);
        Bs[buf][w]   = h2u(fw0.x, fw0.y); Bs[buf][w+1] = h2u(fw0.z, fw0.w);
        Bs[buf][w+2] = h2u(fw1.x, fw1.y); Bs[buf][w+3] = h2u(fw1.z, fw1.w);
    };

    const int nIt = K / 16;
    ldg(0); sts(0);
    __syncthreads();

    for (int it = 0; it < nIt; it++) {
        int buf = it & 1;
        if (it + 1 < nIt) ldg((it + 1) * 16);
        uint32_t aSm = (uint32_t)__cvta_generic_to_shared(&As[buf][0]);
        uint32_t bSm = (uint32_t)__cvta_generic_to_shared(&Bs[buf][0]);
        uint32_t af[4][4], bf[2][4];
        #pragma unroll
        for (int mi = 0; mi < 4; mi++)
            ldsm4(af[mi], aSm + ((wm + mi*16 + aRow)*24 + aK)*2);
        #pragma unroll
        for (int nj = 0; nj < 2; nj++)
            ldsm4(bf[nj], bSm + ((wn + nj*16 + bRow)*24 + bK)*2);
        #pragma unroll
        for (int mi = 0; mi < 4; mi++)
            #pragma unroll
            for (int ni = 0; ni < 4; ni++)
                mma_f16(acc[mi][ni], af[mi], &bf[ni >> 1][(ni & 1) * 2]);
        if (it + 1 < nIt) sts(buf ^ 1);
        __syncthreads();
    }

    #pragma unroll
    for (int mi = 0; mi < 4; mi++) {
        int row = m0 + wm + mi * 16 + g;
        #pragma unroll
        for (int ni = 0; ni < 4; ni++) {
            int col = n0 + wn + ni * 8 + 2 * q4;
            if (row < M)
                *(uint32_t*)(C + (size_t)row*ldc + col) =
                    h2u(acc[mi][ni][0], acc[mi][ni][1]);
            if (row + 8 < M)
                *(uint32_t*)(C + (size_t)(row+8)*ldc + col) =
                    h2u(acc[mi][ni][2], acc[mi][ni][3]);
        }
    }
}

// ---------------------------------------------------------------------------
// V transpose: g_projh v-part [l][n] -> g_vt [z][n][l].
// ---------------------------------------------------------------------------
__global__ void vtrans()
{
    __shared__ __half T[64][72];
    const int z = blockIdx.y, b = z >> 3, h = z & 7;
    const int l0 = blockIdx.x * 64;
    const int t = threadIdx.x;
    const __half* src = g_projh + (size_t)(b * Lq) * QKVq + h*192 + 128;

    for (int i = t; i < 512; i += 128) {
        int row = i >> 3, ch = i & 7;
        uint4 v = *(const uint4*)(src + (size_t)(l0+row)*QKVq + ch*8);
        const __half* hv = (const __half*)&v;
        #pragma unroll
        for (int j = 0; j < 8; j++) T[ch*8 + j][row] = hv[j];
    }
    __syncthreads();
    for (int i = t; i < 512; i += 128) {
        int n = i >> 3, ch = i & 7;
        uint4 v; __half* hv = (__half*)&v;
        #pragma unroll
        for (int j = 0; j < 8; j++) hv[j] = T[n][ch*8 + j];
        *(uint4*)(g_vt + ((size_t)z*64 + n)*Lq + l0 + ch*8) = v;
    }
}

// ---------------------------------------------------------------------------
// Score kernel: AC-first into fp16 smem tile (stride 136), BD RMW with
// diagonal shift, fp16 logits out (plain uint4 copies).
// 512 threads (16 warps 4x4), 2 CTAs/SM.
// ---------------------------------------------------------------------------
__global__ void __launch_bounds__(512, 2)
score_h(const float* __restrict__ ub, const float* __restrict__ vbb)
{
    extern __shared__ char sm_raw[];
    __half* Qh  = (__half*)sm_raw;                // [128][72]
    __half* Kh  = Qh + 128*72;                    // [128][72]
    __half* Ph  = Kh + 128*72;                    // [256][72]
    __half* ACs = Ph + 256*72;                    // [128][136]
    float*  Sc  = (float*)(ACs + 128*136);        // [128]
    float*  Sd  = Sc + 128;                       // [256]

    const int z = blockIdx.z, b = z >> 3, h = z & 7;
    const int q0 = blockIdx.y * 128, k0 = blockIdx.x * 128;
    const __half* Aq = g_projh + (size_t)b*Lq*QKVq + h*192;
    const __half* Bk = Aq + 64;
    const __half* Pk = g_pkh + h*64;
    __half* Lc = g_logith + (size_t)z * Lq * Lq;
    const int j0 = k0 - q0 + 896;

    const int t = threadIdx.x, lane = t & 31, warp = t >> 5;
    const int wm = (warp & 3) * 32, wn = (warp >> 2) * 32;
    const int g = lane >> 2, q4 = lane & 3;

    const int aRow = lane & 15, aK = (lane >> 4) << 3;
    const int bRow = (lane & 7) + ((lane >> 4) << 3), bK = ((lane >> 3) & 1) << 3;

    const uint32_t smQ = (uint32_t)__cvta_generic_to_shared(Qh);
    const uint32_t smK = (uint32_t)__cvta_generic_to_shared(Kh);
    const uint32_t smP = (uint32_t)__cvta_generic_to_shared(Ph);

    #pragma unroll
    for (int p = 0; p < 2; p++) {
        int i = t + p * 512, m = i >> 3, c8 = (i & 7) * 8;
        cpa16(smQ + (uint32_t)(m*144 + c8*2), Aq + (size_t)(q0+m)*QKVq + c8);
    }
    #pragma unroll
    for (int p = 0; p < 2; p++) {
        int i = t + p * 512, m = i >> 3, c8 = (i & 7) * 8;
        cpa16(smK + (uint32_t)(m*144 + c8*2), Bk + (size_t)(k0+m)*QKVq + c8);
    }
    CPA_COMMIT();
    #pragma unroll
    for (int p = 0; p < 4; p++) {
        int i = t + p * 512, m = i >> 3, c8 = (i & 7) * 8;
        cpa16(smP + (uint32_t)(m*144 + c8*2), Pk + (size_t)(j0+m)*Eq + c8);
    }
    CPA_COMMIT();

    float acc[2][4][4];
    auto zero_acc = [&]() {
        #pragma unroll
        for (int mi = 0; mi < 2; mi++)
            #pragma unroll
            for (int ni = 0; ni < 4; ni++)
                #pragma unroll
                for (int e = 0; e < 4; e++) acc[mi][ni][e] = 0.f;
    };

    CPA_WAIT(1);               // Q, K ready
    __syncthreads();

    if (t < 128) {
        const float* uu = ub + h*64;
        float s = 0.f;
        #pragma unroll 8
        for (int dd = 0; dd < 64; dd++) s += uu[dd] * __half2float(Kh[t*72 + dd]);
        Sc[t] = s * SCALEF;
    }

    // ---- AC mma ----
    zero_acc();
    #pragma unroll
    for (int s = 0; s < 4; s++) {
        const int kb = s * 16;
        uint32_t af[2][4], bf[2][4];
        #pragma unroll
        for (int mi = 0; mi < 2; mi++)
            ldsm4(af[mi], smQ + ((wm + mi*16 + aRow)*72 + kb + aK)*2);
        #pragma unroll
        for (int nj = 0; nj < 2; nj++)
            ldsm4(bf[nj], smK + ((wn + nj*16 + bRow)*72 + kb + bK)*2);
        #pragma unroll
        for (int mi = 0; mi < 2; mi++)
            #pragma unroll
            for (int ni = 0; ni < 4; ni++)
                mma_f16(acc[mi][ni], af[mi], &bf[ni >> 1][(ni & 1) * 2]);
    }
    __syncthreads();

    #pragma unroll
    for (int mi = 0; mi < 2; mi++) {
        int row = wm + mi * 16 + g;
        #pragma unroll
        for (int ni = 0; ni < 4; ni++) {
            int c = wn + ni * 8 + 2 * q4;
            *(uint32_t*)&ACs[row*136 + c] =
                h2u(SCALEF*acc[mi][ni][0] + Sc[c], SCALEF*acc[mi][ni][1] + Sc[c+1]);
            *(uint32_t*)&ACs[(row+8)*136 + c] =
                h2u(SCALEF*acc[mi][ni][2] + Sc[c], SCALEF*acc[mi][ni][3] + Sc[c+1]);
        }
    }

    CPA_WAIT(0);               // P ready
    __syncthreads();

    if (t < 256) {
        const float* vv = vbb + h*64;
        float s = 0.f;
        #pragma unroll 8
        for (int dd = 0; dd < 64; dd++) s += vv[dd] * __half2float(Ph[t*72 + dd]);
        Sd[t] = s * SCALEF;
    }
    __syncthreads();

    // ---- BD chunks, RMW into ACs with diagonal shift ----
    auto rmw = [&](int row, int c, float add) {
        if ((unsigned)c < 128u) {
            __half* p = &ACs[row*136 + c];
            *p = __float2half(__half2float(*p) + add);
        }
    };
    #pragma unroll 1
    for (int jc = 0; jc < 2; jc++) {
        zero_acc();
        #pragma unroll
        for (int s = 0; s < 4; s++) {
            const int kb = s * 16;
            uint32_t af[2][4], bf[2][4];
            #pragma unroll
            for (int mi = 0; mi < 2; mi++)
                ldsm4(af[mi], smQ + ((wm + mi*16 + aRow)*72 + kb + aK)*2);
            #pragma unroll
            for (int nj = 0; nj < 2; nj++)
                ldsm4(bf[nj], smP + ((jc*128 + wn + nj*16 + bRow)*72 + kb + bK)*2);
            #pragma unroll
            for (int mi = 0; mi < 2; mi++)
                #pragma unroll
                for (int ni = 0; ni < 4; ni++)
                    mma_f16(acc[mi][ni], af[mi], &bf[ni >> 1][(ni & 1) * 2]);
        }
        #pragma unroll
        for (int mi = 0; mi < 2; mi++) {
            int row = wm + mi * 16 + g;
            #pragma unroll
            for (int ni = 0; ni < 4; ni++) {
                int jcol = jc * 128 + wn + ni * 8 + 2 * q4;
                float d0 = Sd[jcol], d1 = Sd[jcol + 1];
                rmw(row, jcol + row - 127,     SCALEF*acc[mi][ni][0] + d0);
                rmw(row, jcol + 1 + row - 127, SCALEF*acc[mi][ni][1] + d1);
                int row2 = row + 8;
                rmw(row2, jcol + row2 - 127,     SCALEF*acc[mi][ni][2] + d0);
                rmw(row2, jcol + 1 + row2 - 127, SCALEF*acc[mi][ni][3] + d1);
            }
        }
    }
    __syncthreads();

    // ---- final store: fp16 logits (uint4 copies; rows 16B-aligned) ----
    for (int i = t; i < 128 * 16; i += 512) {
        int row = i >> 4, c8 = (i & 15) * 8;
        *(uint4*)(Lc + (size_t)(q0+row)*Lq + k0 + c8) = *(uint4*)&ACs[row*136 + c8];
    }
}

// ---------------------------------------------------------------------------
// Softmax: fp16 logits in -> fp32 attn out + fp16 normalized probs in-place.
// 128 threads per row; each thread owns 8 elements.
// ---------------------------------------------------------------------------
__global__ void softmax_h(float* __restrict__ attn)
{
    __half* Lr = g_logith + (size_t)blockIdx.x * Lq;
    float*  Or = attn     + (size_t)blockIdx.x * Lq;
    const int t = threadIdx.x;

    uint4 raw = *(uint4*)(Lr + t * 8);
    __half2* hp = (__half2*)&raw;
    float f[8];
    #pragma unroll
    for (int j = 0; j < 4; j++) {
        float2 fx = __half22float2(hp[j]);
        f[2*j] = fx.x; f[2*j+1] = fx.y;
    }

    float m = f[0];
    #pragma unroll
    for (int j = 1; j < 8; j++) m = fmaxf(m, f[j]);
    #pragma unroll
    for (int o = 16; o > 0; o >>= 1) m = fmaxf(m, __shfl_xor_sync(0xffffffffu, m, o));
    __shared__ float red[4];
    if ((t & 31) == 0) red[t >> 5] = m;
    __syncthreads();
    float bm = fmaxf(fmaxf(red[0], red[1]), fmaxf(red[2], red[3]));

    float s = 0.f;
    #pragma unroll
    for (int j = 0; j < 8; j++) { f[j] = expf(f[j] - bm); s += f[j]; }
    #pragma unroll
    for (int o = 16; o > 0; o >>= 1) s += __shfl_xor_sync(0xffffffffu, s, o);
    __syncthreads();
    if ((t & 31) == 0) red[t >> 5] = s;
    __syncthreads();
    float inv = 1.0f / (red[0] + red[1] + red[2] + red[3]);

    #pragma unroll
    for (int j = 0; j < 8; j++) f[j] *= inv;
    *(float4*)(Or + t*8)     = make_float4(f[0], f[1], f[2], f[3]);
    *(float4*)(Or + t*8 + 4) = make_float4(f[4], f[5], f[6], f[7]);
    uint4 packed;
    uint32_t* pw = (uint32_t*)&packed;
    #pragma unroll
    for (int j = 0; j < 4; j++) pw[j] = h2u(f[2*j], f[2*j+1]);
    *(uint4*)(Lr + t * 8) = packed;
}

// ---------------------------------------------------------------------------
// ctx = probs(fp16) @ V (fp16 mma + ldmatrix). B=g_vt half [n][k].
// ---------------------------------------------------------------------------
__global__ void __launch_bounds__(256, 2)
ctx_h()
{
    const int z = blockIdx.z, b = z >> 3, h = z & 7;
    const __half* A  = g_logith + (size_t)z * Lq * Lq;
    const __half* Vt = g_vt + (size_t)z * 64 * Lq;
    __half*       Cm = g_ctxh + (size_t)b*Lq*Eq + h*64;

    __shared__ uint32_t As[2][128 * GS];
    __shared__ uint32_t Bs[2][64 * GS];
    const int m0 = blockIdx.y * 128;
    const int t = threadIdx.x, lane = t & 31, warp = t >> 5;
    const int wm = (warp & 3) * 32, wn = (warp >> 2) * 32;
    const int g = lane >> 2, q4 = lane & 3;
    const int lr = t >> 1, kh = (t & 1) * 8;

    const int aRow = lane & 15, aK = (lane >> 4) << 3;
    const int bRow = (lane & 7) + ((lane >> 4) << 3), bK = ((lane >> 3) & 1) << 3;

    float acc[2][4][4] = {};
    uint4 av, bv;

    auto ldg = [&](int k0) {
        av = *(const uint4*)(A + (size_t)(m0+lr)*Lq + k0 + kh);
        if (t < 128)
            bv = *(const uint4*)(Vt + (size_t)(t >> 1)*Lq + k0 + kh);
    };
    auto sts = [&](int buf) {
        int w = lr * GS + (kh >> 1);
        As[buf][w]   = av.x; As[buf][w+1] = av.y;
        As[buf][w+2] = av.z; As[buf][w+3] = av.w;
        if (t < 128) {
            int wb = (t >> 1) * GS + (kh >> 1);
            Bs[buf][wb]   = bv.x; Bs[buf][wb+1] = bv.y;
            Bs[buf][wb+2] = bv.z; Bs[buf][wb+3] = bv.w;
        }
    };

    ldg(0); sts(0);
    __syncthreads();

    for (int it = 0; it < 64; it++) {
        int buf = it & 1;
        if (it + 1 < 64) ldg((it + 1) * 16);
        uint32_t aSm = (uint32_t)__cvta_generic_to_shared(&As[buf][0]);
        uint32_t bSm = (uint32_t)__cvta_generic_to_shared(&Bs[buf][0]);
        uint32_t af[2][4], bf[2][4];
        #pragma unroll
        for (int mi = 0; mi < 2; mi++)
            ldsm4(af[mi], aSm + ((wm + mi*16 + aRow)*24 + aK)*2);
        #pragma unroll
        for (int nj = 0; nj < 2; nj++)
            ldsm4(bf[nj], bSm + ((wn + nj*16 + bRow)*24 + bK)*2);
        #pragma unroll
        for (int mi = 0; mi < 2; mi++)
            #pragma unroll
            for (int ni = 0; ni < 4; ni++)
                mma_f16(acc[mi][ni], af[mi], &bf[ni >> 1][(ni & 1) * 2]);
        if (it + 1 < 64) sts(buf ^ 1);
        __syncthreads();
    }

    #pragma unroll
    for (int mi = 0; mi < 2; mi++) {
        int row = m0 + wm + mi * 16 + g;
        #pragma unroll
        for (int ni = 0; ni < 4; ni++) {
            int col = wn + ni * 8 + 2 * q4;
            *(uint32_t*)(Cm + (size_t)row*Eq + col) =
                h2u(acc[mi][ni][0], acc[mi][ni][1]);
            *(uint32_t*)(Cm + (size_t)(row+8)*Eq + col) =
                h2u(acc[mi][ni][2], acc[mi][ni][3]);
        }
    }
}

// ---------------------------------------------------------------------------
// Out projection: out = ctxh @ W^T + bias.
// ---------------------------------------------------------------------------
__global__ void __launch_bounds__(256, 2)
gemm_out(const __half* __restrict__ A, const float* __restrict__ W,
         const float* __restrict__ bias, float* __restrict__ C,
         int M, int N, int K)
{
    __shared__ uint32_t As[2][128 * GS];
    __shared__ uint32_t Bs[2][128 * GS];
    const int m0 = blockIdx.y * 128, n0 = blockIdx.x * 128;
    const int t = threadIdx.x, lane = t & 31, warp = t >> 5;
    const int wm = (warp & 1) * 64, wn = (warp >> 1) * 32;
    const int g = lane >> 2, q4 = lane & 3;
    const int lr = t >> 1, kh = (t & 1) * 8;

    const int aRow = lane & 15, aK = (lane >> 4) << 3;
    const int bRow = (lane & 7) + ((lane >> 4) << 3), bK = ((lane >> 3) & 1) << 3;

    float acc[4][4][4] = {};
    uint4 av;
    float4 fw0, fw1;

    auto ldg = [&](int k0) {
        av  = *(const uint4*)(A + (size_t)(m0+lr)*K + k0 + kh);
        fw0 = *(const float4*)(W + (size_t)(n0+lr)*K + k0 + kh);
        fw1 = *(const float4*)(W + (size_t)(n0+lr)*K + k0 + kh + 4);
    };
    auto sts = [&](int buf) {
        int w = lr * GS + (kh >> 1);
        As[buf][w]   = av.x; As[buf][w+1] = av.y;
        As[buf][w+2] = av.z; As[buf][w+3] = av.w;
        Bs[buf][w]   = h2u(fw0.x, fw0.y); Bs[buf][w+1] = h2u(fw0.z, fw0.w);
        Bs[buf][w+2] = h2u(fw1.x, fw1.y); Bs[buf][w+3] = h2u(fw1.z, fw1.w);
    };

    const int nIt = K / 16;
    ldg(0); sts(0);
    __syncthreads();

    for (int it = 0; it < nIt; it++) {
        int buf = it & 1;
        if (it + 1 < nIt) ldg((it + 1) * 16);
        uint32_t aSm = (uint32_t)__cvta_generic_to_shared(&As[buf][0]);
        uint32_t bSm = (uint32_t)__cvta_generic_to_shared(&Bs[buf][0]);
        uint32_t af[4][4], bf[2][4];
        #pragma unroll
        for (int mi = 0; mi < 4; mi++)
            ldsm4(af[mi], aSm + ((wm + mi*16 + aRow)*24 + aK)*2);
        #pragma unroll
        for (int nj = 0; nj < 2; nj++)
            ldsm4(bf[nj], bSm + ((wn + nj*16 + bRow)*24 + bK)*2);
        #pragma unroll
        for (int mi = 0; mi < 4; mi++)
            #pragma unroll
            for (int ni = 0; ni < 4; ni++)
                mma_f16(acc[mi][ni], af[mi], &bf[ni >> 1][(ni & 1) * 2]);
        if (it + 1 < nIt) sts(buf ^ 1);
        __syncthreads();
    }

    #pragma unroll
    for (int mi = 0; mi < 4; mi++) {
        int row = m0 + wm + mi * 16 + g;
        #pragma unroll
        for (int ni = 0; ni < 4; ni++) {
            int col = n0 + wn + ni * 8 + 2 * q4;
            float b0 = bias[col], b1 = bias[col+1];
            *(float2*)(C + (size_t)row*N + col) =
                make_float2(acc[mi][ni][0] + b0, acc[mi][ni][1] + b1);
            *(float2*)(C + (size_t)(row+8)*N + col) =
                make_float2(acc[mi][ni][2] + b0, acc[mi][ni][3] + b1);
        }
    }
}

// ---------------------------------------------------------------------------
extern "C" void kernel_launch(void* const* d_in, const int* in_sizes, int n_in,
                              void* d_out, int out_size)
{
    const float* x     = (const float*)d_in[0];
    const float* pos   = (const float*)d_in[1];
    const float* w_in  = (const float*)d_in[2];
    const float* w_pos = (const float*)d_in[3];
    const float* w_out = (const float*)d_in[4];
    const float* b_out = (const float*)d_in[5];
    const float* ub    = (const float*)d_in[6];
    const float* vbb   = (const float*)d_in[7];
    float* out = (float*)d_out;

    __half *projh, *pkh, *ctxh;
    float *attn_fb;
    cudaGetSymbolAddress((void**)&projh,   g_projh);
    cudaGetSymbolAddress((void**)&pkh,     g_pkh);
    cudaGetSymbolAddress((void**)&ctxh,    g_ctxh);
    cudaGetSymbolAddress((void**)&attn_fb, g_attn_fb);

    cudaFuncSetAttribute(score_h, cudaFuncAttributeMaxDynamicSharedMemorySize,
                         SCORE_SMEM);

    const size_t OUT_E  = (size_t)BLq * Eq;
    const size_t ATTN_E = (size_t)Bq * Hq * Lq * Lq;
    float* attn = ((size_t)out_size >= OUT_E + ATTN_E) ? (out + OUT_E) : attn_fb;

    // 1) QKV projection -> fp16
    gemm_h<<<dim3(QKVq/128, BLq/128), 256>>>(x, w_in, projh,
                                             BLq, QKVq, Eq, Eq, Eq, QKVq);
    // 2) positional keys -> fp16
    gemm_h<<<dim3(Eq/128, (Pq+127)/128), 256>>>(pos, w_pos, pkh,
                                                Pq, Eq, Eq, Eq, Eq, Eq);
    // 3) V transpose
    vtrans<<<dim3(Lq/64, Bq*Hq), 128>>>();
    // 4) fused AC + shifted BD logits -> fp16
    score_h<<<dim3(Lq/128, Lq/128, Bq*Hq), 512, SCORE_SMEM>>>(ub, vbb);
    // 5) softmax: fp16 in -> fp32 attn out + fp16 probs in-place
    softmax_h<<<Bq*Hq*Lq, 128>>>(attn);
    // 6) ctx = probs @ V -> fp16
    ctx_h<<<dim3(1, Lq/128, Bq*Hq), 256>>>();
    // 7) out projection + bias
    gemm_out<<<dim3(Eq/128, BLq/128), 256>>>(ctxh, w_out, b_out, out,
                                             BLq, Eq, Eq);
}

// round 17
// speedup vs baseline: 2.1218x; 1.0478x over previous
#include <cuda_runtime.h>
#include <cuda_bf16.h>
#include <cuda_fp16.h>
#include <cstdint>
#include <math.h>

#define Bq   8
#define Lq   1024
#define Eq   512
#define Hq   8
#define HDq  64
#define Pq   2047
#define BLq  8192
#define QKVq 1536
#define SCALEF 0.044194173824159216f  // 1/sqrt(512)

__device__ __half g_projh[(size_t)BLq * QKVq];
__device__ __half g_pkh[(size_t)(Pq + 1) * Eq];        // 2048 rows (pad)
__device__ __half g_vt[(size_t)Bq * Hq * HDq * Lq];
__device__ __half g_ctxh[(size_t)BLq * Eq];
__device__ __half g_logith[(size_t)Bq * Hq * Lq * Lq];
__device__ float  g_attn_fb[(size_t)Bq * Hq * Lq * Lq];
// fp16 copies of inputs
__device__ __half g_xh[(size_t)BLq * Eq];
__device__ __half g_posh[(size_t)2048 * Eq];           // padded, row 2047 = 0
__device__ __half g_winh[(size_t)QKVq * Eq];
__device__ __half g_wposh[(size_t)Eq * Eq];
__device__ __half g_wouth[(size_t)Eq * Eq];

#define SCORE_SMEM ((128*72 + 128*72 + 256*72)*2 + 128*136*2 + 128*4 + 256*4) // 110080

__device__ __forceinline__ void mma_f16(float c[4], const uint32_t a[4],
                                        const uint32_t b[2]) {
    asm volatile(
        "mma.sync.aligned.m16n8k16.row.col.f32.f16.f16.f32 "
        "{%0,%1,%2,%3}, {%4,%5,%6,%7}, {%8,%9}, {%0,%1,%2,%3};"
        : "+f"(c[0]), "+f"(c[1]), "+f"(c[2]), "+f"(c[3])
        : "r"(a[0]), "r"(a[1]), "r"(a[2]), "r"(a[3]), "r"(b[0]), "r"(b[1]));
}

__device__ __forceinline__ void ldsm4(uint32_t r[4], uint32_t addr) {
    asm volatile("ldmatrix.sync.aligned.m8n8.x4.shared.b16 {%0,%1,%2,%3}, [%4];"
                 : "=r"(r[0]), "=r"(r[1]), "=r"(r[2]), "=r"(r[3]) : "r"(addr));
}

__device__ __forceinline__ uint32_t h2u(float x, float y) {
    __half2 h = __floats2half2_rn(x, y);
    return *(uint32_t*)&h;
}

__device__ __forceinline__ void cpa16(uint32_t dst_smem, const void* src) {
    asm volatile("cp.async.cg.shared.global [%0], [%1], 16;"
                 :: "r"(dst_smem), "l"(src));
}
#define CPA_COMMIT() asm volatile("cp.async.commit_group;")
#define CPA_WAIT(n)  asm volatile("cp.async.wait_group %0;" :: "n"(n))

#define GS 12   // smem row stride in words (24 halves)

// ---------------------------------------------------------------------------
// float -> half conversion (8 elems/thread); zero-fills [n_src, n_dst).
// ---------------------------------------------------------------------------
__global__ void f2h_kernel(const float* __restrict__ src, __half* __restrict__ dst,
                           int n_src, int n_dst)
{
    int i = (blockIdx.x * blockDim.x + threadIdx.x) * 8;
    if (i >= n_dst) return;
    if (i + 8 <= n_src) {
        float4 a = *(const float4*)(src + i);
        float4 b = *(const float4*)(src + i + 4);
        uint4 o; uint32_t* ow = (uint32_t*)&o;
        ow[0] = h2u(a.x, a.y); ow[1] = h2u(a.z, a.w);
        ow[2] = h2u(b.x, b.y); ow[3] = h2u(b.z, b.w);
        *(uint4*)(dst + i) = o;
    } else {
        for (int j = i; j < i + 8 && j < n_dst; j++)
            dst[j] = (j < n_src) ? __float2half(src[j]) : __half(0.f);
    }
}

// ---------------------------------------------------------------------------
// Half GEMM: C[M,N] = A @ W^T, all half in gmem, C half. cp.async loaders.
// M, N multiples of 128; K multiple of 16.
// ---------------------------------------------------------------------------
__global__ void __launch_bounds__(256, 2)
gemm_hh(const __half* __restrict__ A, const __half* __restrict__ W,
        __half* __restrict__ C, int M, int N, int K, int ldc)
{
    __shared__ uint32_t As[2][128 * GS];
    __shared__ uint32_t Bs[2][128 * GS];
    const int m0 = blockIdx.y * 128, n0 = blockIdx.x * 128;
    const int t = threadIdx.x, lane = t & 31, warp = t >> 5;
    const int wm = (warp & 1) * 64, wn = (warp >> 1) * 32;
    const int g = lane >> 2, q4 = lane & 3;
    const int lr = t >> 1, kq = t & 1;

    const int aRow = lane & 15, aK = (lane >> 4) << 3;
    const int bRow = (lane & 7) + ((lane >> 4) << 3), bK = ((lane >> 3) & 1) << 3;

    const uint32_t aBase = (uint32_t)__cvta_generic_to_shared(&As[0][0]);
    const uint32_t bBase = (uint32_t)__cvta_generic_to_shared(&Bs[0][0]);

    float acc[4][4][4] = {};

    auto load = [&](int stage, int k0) {
        uint32_t off = (uint32_t)stage * (128 * GS * 4) + lr * 48 + kq * 16;
        cpa16(aBase + off, A + (size_t)(m0 + lr) * K + k0 + kq * 8);
        cpa16(bBase + off, W + (size_t)(n0 + lr) * K + k0 + kq * 8);
        CPA_COMMIT();
    };

    const int nIt = K / 16;
    load(0, 0);

    for (int it = 0; it < nIt; it++) {
        if (it + 1 < nIt) load((it + 1) & 1, (it + 1) * 16);
        if (it + 1 < nIt) { CPA_WAIT(1); } else { CPA_WAIT(0); }
        __syncthreads();
        int buf = it & 1;
        uint32_t aSm = aBase + (uint32_t)buf * (128 * GS * 4);
        uint32_t bSm = bBase + (uint32_t)buf * (128 * GS * 4);
        uint32_t af[4][4], bf[2][4];
        #pragma unroll
        for (int mi = 0; mi < 4; mi++)
            ldsm4(af[mi], aSm + ((wm + mi*16 + aRow)*24 + aK)*2);
        #pragma unroll
        for (int nj = 0; nj < 2; nj++)
            ldsm4(bf[nj], bSm + ((wn + nj*16 + bRow)*24 + bK)*2);
        #pragma unroll
        for (int mi = 0; mi < 4; mi++)
            #pragma unroll
            for (int ni = 0; ni < 4; ni++)
                mma_f16(acc[mi][ni], af[mi], &bf[ni >> 1][(ni & 1) * 2]);
        __syncthreads();
    }

    #pragma unroll
    for (int mi = 0; mi < 4; mi++) {
        int row = m0 + wm + mi * 16 + g;
        #pragma unroll
        for (int ni = 0; ni < 4; ni++) {
            int col = n0 + wn + ni * 8 + 2 * q4;
            *(uint32_t*)(C + (size_t)row*ldc + col) =
                h2u(acc[mi][ni][0], acc[mi][ni][1]);
            *(uint32_t*)(C + (size_t)(row+8)*ldc + col) =
                h2u(acc[mi][ni][2], acc[mi][ni][3]);
        }
    }
}

// ---------------------------------------------------------------------------
// Half GEMM with fp32 output + bias (out projection).
// ---------------------------------------------------------------------------
__global__ void __launch_bounds__(256, 2)
gemm_hf(const __half* __restrict__ A, const __half* __restrict__ W,
        const float* __restrict__ bias, float* __restrict__ C,
        int M, int N, int K)
{
    __shared__ uint32_t As[2][128 * GS];
    __shared__ uint32_t Bs[2][128 * GS];
    const int m0 = blockIdx.y * 128, n0 = blockIdx.x * 128;
    const int t = threadIdx.x, lane = t & 31, warp = t >> 5;
    const int wm = (warp & 1) * 64, wn = (warp >> 1) * 32;
    const int g = lane >> 2, q4 = lane & 3;
    const int lr = t >> 1, kq = t & 1;

    const int aRow = lane & 15, aK = (lane >> 4) << 3;
    const int bRow = (lane & 7) + ((lane >> 4) << 3), bK = ((lane >> 3) & 1) << 3;

    const uint32_t aBase = (uint32_t)__cvta_generic_to_shared(&As[0][0]);
    const uint32_t bBase = (uint32_t)__cvta_generic_to_shared(&Bs[0][0]);

    float acc[4][4][4] = {};

    auto load = [&](int stage, int k0) {
        uint32_t off = (uint32_t)stage * (128 * GS * 4) + lr * 48 + kq * 16;
        cpa16(aBase + off, A + (size_t)(m0 + lr) * K + k0 + kq * 8);
        cpa16(bBase + off, W + (size_t)(n0 + lr) * K + k0 + kq * 8);
        CPA_COMMIT();
    };

    const int nIt = K / 16;
    load(0, 0);

    for (int it = 0; it < nIt; it++) {
        if (it + 1 < nIt) load((it + 1) & 1, (it + 1) * 16);
        if (it + 1 < nIt) { CPA_WAIT(1); } else { CPA_WAIT(0); }
        __syncthreads();
        int buf = it & 1;
        uint32_t aSm = aBase + (uint32_t)buf * (128 * GS * 4);
        uint32_t bSm = bBase + (uint32_t)buf * (128 * GS * 4);
        uint32_t af[4][4], bf[2][4];
        #pragma unroll
        for (int mi = 0; mi < 4; mi++)
            ldsm4(af[mi], aSm + ((wm + mi*16 + aRow)*24 + aK)*2);
        #pragma unroll
        for (int nj = 0; nj < 2; nj++)
            ldsm4(bf[nj], bSm + ((wn + nj*16 + bRow)*24 + bK)*2);
        #pragma unroll
        for (int mi = 0; mi < 4; mi++)
            #pragma unroll
            for (int ni = 0; ni < 4; ni++)
                mma_f16(acc[mi][ni], af[mi], &bf[ni >> 1][(ni & 1) * 2]);
        __syncthreads();
    }

    #pragma unroll
    for (int mi = 0; mi < 4; mi++) {
        int row = m0 + wm + mi * 16 + g;
        #pragma unroll
        for (int ni = 0; ni < 4; ni++) {
            int col = n0 + wn + ni * 8 + 2 * q4;
            float b0 = bias[col], b1 = bias[col+1];
            *(float2*)(C + (size_t)row*N + col) =
                make_float2(acc[mi][ni][0] + b0, acc[mi][ni][1] + b1);
            *(float2*)(C + (size_t)(row+8)*N + col) =
                make_float2(acc[mi][ni][2] + b0, acc[mi][ni][3] + b1);
        }
    }
}

// ---------------------------------------------------------------------------
// V transpose: g_projh v-part [l][n] -> g_vt [z][n][l].
// ---------------------------------------------------------------------------
__global__ void vtrans()
{
    __shared__ __half T[64][72];
    const int z = blockIdx.y, b = z >> 3, h = z & 7;
    const int l0 = blockIdx.x * 64;
    const int t = threadIdx.x;
    const __half* src = g_projh + (size_t)(b * Lq) * QKVq + h*192 + 128;

    for (int i = t; i < 512; i += 128) {
        int row = i >> 3, ch = i & 7;
        uint4 v = *(const uint4*)(src + (size_t)(l0+row)*QKVq + ch*8);
        const __half* hv = (const __half*)&v;
        #pragma unroll
        for (int j = 0; j < 8; j++) T[ch*8 + j][row] = hv[j];
    }
    __syncthreads();
    for (int i = t; i < 512; i += 128) {
        int n = i >> 3, ch = i & 7;
        uint4 v; __half* hv = (__half*)&v;
        #pragma unroll
        for (int j = 0; j < 8; j++) hv[j] = T[n][ch*8 + j];
        *(uint4*)(g_vt + ((size_t)z*64 + n)*Lq + l0 + ch*8) = v;
    }
}

// ---------------------------------------------------------------------------
// Score kernel: AC + folded d[] into fp16 smem tile, BD parity-vectorized RMW,
// fp16 logits out. 512 threads (16 warps 4x4), 2 CTAs/SM.
// ---------------------------------------------------------------------------
__global__ void __launch_bounds__(512, 2)
score_h(const float* __restrict__ ub, const float* __restrict__ vbb)
{
    extern __shared__ char sm_raw[];
    __half* Qh  = (__half*)sm_raw;                // [128][72]
    __half* Kh  = Qh + 128*72;                    // [128][72]
    __half* Ph  = Kh + 128*72;                    // [256][72]
    __half* ACs = Ph + 256*72;                    // [128][136]
    float*  Sc  = (float*)(ACs + 128*136);        // [128]
    float*  Sd  = Sc + 128;                       // [256]

    const int z = blockIdx.z, b = z >> 3, h = z & 7;
    const int q0 = blockIdx.y * 128, k0 = blockIdx.x * 128;
    const __half* Aq = g_projh + (size_t)b*Lq*QKVq + h*192;
    const __half* Bk = Aq + 64;
    const __half* Pk = g_pkh + h*64;
    __half* Lc = g_logith + (size_t)z * Lq * Lq;
    const int j0 = k0 - q0 + 896;

    const int t = threadIdx.x, lane = t & 31, warp = t >> 5;
    const int wm = (warp & 3) * 32, wn = (warp >> 2) * 32;
    const int g = lane >> 2, q4 = lane & 3;

    const int aRow = lane & 15, aK = (lane >> 4) << 3;
    const int bRow = (lane & 7) + ((lane >> 4) << 3), bK = ((lane >> 3) & 1) << 3;

    const uint32_t smQ = (uint32_t)__cvta_generic_to_shared(Qh);
    const uint32_t smK = (uint32_t)__cvta_generic_to_shared(Kh);
    const uint32_t smP = (uint32_t)__cvta_generic_to_shared(Ph);

    #pragma unroll
    for (int p = 0; p < 2; p++) {
        int i = t + p * 512, m = i >> 3, c8 = (i & 7) * 8;
        cpa16(smQ + (uint32_t)(m*144 + c8*2), Aq + (size_t)(q0+m)*QKVq + c8);
    }
    #pragma unroll
    for (int p = 0; p < 2; p++) {
        int i = t + p * 512, m = i >> 3, c8 = (i & 7) * 8;
        cpa16(smK + (uint32_t)(m*144 + c8*2), Bk + (size_t)(k0+m)*QKVq + c8);
    }
    CPA_COMMIT();
    #pragma unroll
    for (int p = 0; p < 4; p++) {
        int i = t + p * 512, m = i >> 3, c8 = (i & 7) * 8;
        cpa16(smP + (uint32_t)(m*144 + c8*2), Pk + (size_t)(j0+m)*Eq + c8);
    }
    CPA_COMMIT();

    float acc[2][4][4];
    auto zero_acc = [&]() {
        #pragma unroll
        for (int mi = 0; mi < 2; mi++)
            #pragma unroll
            for (int ni = 0; ni < 4; ni++)
                #pragma unroll
                for (int e = 0; e < 4; e++) acc[mi][ni][e] = 0.f;
    };

    CPA_WAIT(1);               // Q, K ready
    __syncthreads();

    if (t < 128) {
        const float* uu = ub + h*64;
        float s = 0.f;
        #pragma unroll 8
        for (int dd = 0; dd < 64; dd++) s += uu[dd] * __half2float(Kh[t*72 + dd]);
        Sc[t] = s * SCALEF;
    }

    // ---- AC mma (P load still in flight) ----
    zero_acc();
    #pragma unroll
    for (int s = 0; s < 4; s++) {
        const int kb = s * 16;
        uint32_t af[2][4], bf[2][4];
        #pragma unroll
        for (int mi = 0; mi < 2; mi++)
            ldsm4(af[mi], smQ + ((wm + mi*16 + aRow)*72 + kb + aK)*2);
        #pragma unroll
        for (int nj = 0; nj < 2; nj++)
            ldsm4(bf[nj], smK + ((wn + nj*16 + bRow)*72 + kb + bK)*2);
        #pragma unroll
        for (int mi = 0; mi < 2; mi++)
            #pragma unroll
            for (int ni = 0; ni < 4; ni++)
                mma_f16(acc[mi][ni], af[mi], &bf[ni >> 1][(ni & 1) * 2]);
    }

    CPA_WAIT(0);               // P ready
    __syncthreads();           // P + Sc visible

    // d[j] = s * (v . P_j)
    if (t < 256) {
        const float* vv = vbb + h*64;
        float s = 0.f;
        #pragma unroll 8
        for (int dd = 0; dd < 64; dd++) s += vv[dd] * __half2float(Ph[t*72 + dd]);
        Sd[t] = s * SCALEF;
    }
    __syncthreads();           // Sd visible

    // AC epilogue: write s*AC + c[k] + d[c-row+127] (d folded here, exact)
    #pragma unroll
    for (int mi = 0; mi < 2; mi++) {
        int row = wm + mi * 16 + g;
        #pragma unroll
        for (int ni = 0; ni < 4; ni++) {
            int c = wn + ni * 8 + 2 * q4;
            int jb = c - row + 127;        // in [0, 254]
            *(uint32_t*)&ACs[row*136 + c] =
                h2u(SCALEF*acc[mi][ni][0] + Sc[c]   + Sd[jb],
                    SCALEF*acc[mi][ni][1] + Sc[c+1] + Sd[jb+1]);
            int row2 = row + 8, jb2 = jb - 8;
            *(uint32_t*)&ACs[row2*136 + c] =
                h2u(SCALEF*acc[mi][ni][2] + Sc[c]   + Sd[jb2],
                    SCALEF*acc[mi][ni][3] + Sc[c+1] + Sd[jb2+1]);
        }
    }
    __syncthreads();           // ACs complete before RMW

    // ---- BD chunks, parity-vectorized RMW into ACs ----
    auto rmwpair = [&](int row, int c, float a0, float a1) {
        __half* base = &ACs[row*136];
        if (((c & 1) == 0) && (unsigned)c < 127u) {
            __half2* p = (__half2*)(base + c);
            float2 cur = __half22float2(*p);
            *p = __floats2half2_rn(cur.x + a0, cur.y + a1);
        } else {
            if ((unsigned)c < 128u) {
                __half* p = base + c;
                *p = __float2half(__half2float(*p) + a0);
            }
            if ((unsigned)(c + 1) < 128u) {
                __half* p = base + c + 1;
                *p = __float2half(__half2float(*p) + a1);
            }
        }
    };
    #pragma unroll 1
    for (int jc = 0; jc < 2; jc++) {
        zero_acc();
        #pragma unroll
        for (int s = 0; s < 4; s++) {
            const int kb = s * 16;
            uint32_t af[2][4], bf[2][4];
            #pragma unroll
            for (int mi = 0; mi < 2; mi++)
                ldsm4(af[mi], smQ + ((wm + mi*16 + aRow)*72 + kb + aK)*2);
            #pragma unroll
            for (int nj = 0; nj < 2; nj++)
                ldsm4(bf[nj], smP + ((jc*128 + wn + nj*16 + bRow)*72 + kb + bK)*2);
            #pragma unroll
            for (int mi = 0; mi < 2; mi++)
                #pragma unroll
                for (int ni = 0; ni < 4; ni++)
                    mma_f16(acc[mi][ni], af[mi], &bf[ni >> 1][(ni & 1) * 2]);
        }
        #pragma unroll
        for (int mi = 0; mi < 2; mi++) {
            int row = wm + mi * 16 + g;
            #pragma unroll
            for (int ni = 0; ni < 4; ni++) {
                int jcol = jc * 128 + wn + ni * 8 + 2 * q4;
                rmwpair(row, jcol + row - 127,
                        SCALEF*acc[mi][ni][0], SCALEF*acc[mi][ni][1]);
                int row2 = row + 8;
                rmwpair(row2, jcol + row2 - 127,
                        SCALEF*acc[mi][ni][2], SCALEF*acc[mi][ni][3]);
            }
        }
    }
    __syncthreads();

    // ---- final store: fp16 logits ----
    for (int i = t; i < 128 * 16; i += 512) {
        int row = i >> 4, c8 = (i & 15) * 8;
        *(uint4*)(Lc + (size_t)(q0+row)*Lq + k0 + c8) = *(uint4*)&ACs[row*136 + c8];
    }
}

// ---------------------------------------------------------------------------
// Softmax: fp16 logits -> fp32 attn out + fp16 probs in-place.
// ---------------------------------------------------------------------------
__global__ void softmax_h(float* __restrict__ attn)
{
    __half* Lr = g_logith + (size_t)blockIdx.x * Lq;
    float*  Or = attn     + (size_t)blockIdx.x * Lq;
    const int t = threadIdx.x;

    uint4 raw = *(uint4*)(Lr + t * 8);
    __half2* hp = (__half2*)&raw;
    float f[8];
    #pragma unroll
    for (int j = 0; j < 4; j++) {
        float2 fx = __half22float2(hp[j]);
        f[2*j] = fx.x; f[2*j+1] = fx.y;
    }

    float m = f[0];
    #pragma unroll
    for (int j = 1; j < 8; j++) m = fmaxf(m, f[j]);
    #pragma unroll
    for (int o = 16; o > 0; o >>= 1) m = fmaxf(m, __shfl_xor_sync(0xffffffffu, m, o));
    __shared__ float red[4];
    if ((t & 31) == 0) red[t >> 5] = m;
    __syncthreads();
    float bm = fmaxf(fmaxf(red[0], red[1]), fmaxf(red[2], red[3]));

    float s = 0.f;
    #pragma unroll
    for (int j = 0; j < 8; j++) { f[j] = expf(f[j] - bm); s += f[j]; }
    #pragma unroll
    for (int o = 16; o > 0; o >>= 1) s += __shfl_xor_sync(0xffffffffu, s, o);
    __syncthreads();
    if ((t & 31) == 0) red[t >> 5] = s;
    __syncthreads();
    float inv = 1.0f / (red[0] + red[1] + red[2] + red[3]);

    #pragma unroll
    for (int j = 0; j < 8; j++) f[j] *= inv;
    *(float4*)(Or + t*8)     = make_float4(f[0], f[1], f[2], f[3]);
    *(float4*)(Or + t*8 + 4) = make_float4(f[4], f[5], f[6], f[7]);
    uint4 packed;
    uint32_t* pw = (uint32_t*)&packed;
    #pragma unroll
    for (int j = 0; j < 4; j++) pw[j] = h2u(f[2*j], f[2*j+1]);
    *(uint4*)(Lr + t * 8) = packed;
}

// ---------------------------------------------------------------------------
// ctx = probs(fp16) @ V (fp16 mma + ldmatrix). B=g_vt half [n][k].
// ---------------------------------------------------------------------------
__global__ void __launch_bounds__(256, 2)
ctx_h()
{
    const int z = blockIdx.z, b = z >> 3, h = z & 7;
    const __half* A  = g_logith + (size_t)z * Lq * Lq;
    const __half* Vt = g_vt + (size_t)z * 64 * Lq;
    __half*       Cm = g_ctxh + (size_t)b*Lq*Eq + h*64;

    __shared__ uint32_t As[2][128 * GS];
    __shared__ uint32_t Bs[2][64 * GS];
    const int m0 = blockIdx.y * 128;
    const int t = threadIdx.x, lane = t & 31, warp = t >> 5;
    const int wm = (warp & 3) * 32, wn = (warp >> 2) * 32;
    const int g = lane >> 2, q4 = lane & 3;
    const int lr = t >> 1, kh = (t & 1) * 8;

    const int aRow = lane & 15, aK = (lane >> 4) << 3;
    const int bRow = (lane & 7) + ((lane >> 4) << 3), bK = ((lane >> 3) & 1) << 3;

    float acc[2][4][4] = {};
    uint4 av, bv;

    auto ldg = [&](int k0) {
        av = *(const uint4*)(A + (size_t)(m0+lr)*Lq + k0 + kh);
        if (t < 128)
            bv = *(const uint4*)(Vt + (size_t)(t >> 1)*Lq + k0 + kh);
    };
    auto sts = [&](int buf) {
        int w = lr * GS + (kh >> 1);
        As[buf][w]   = av.x; As[buf][w+1] = av.y;
        As[buf][w+2] = av.z; As[buf][w+3] = av.w;
        if (t < 128) {
            int wb = (t >> 1) * GS + (kh >> 1);
            Bs[buf][wb]   = bv.x; Bs[buf][wb+1] = bv.y;
            Bs[buf][wb+2] = bv.z; Bs[buf][wb+3] = bv.w;
        }
    };

    ldg(0); sts(0);
    __syncthreads();

    for (int it = 0; it < 64; it++) {
        int buf = it & 1;
        if (it + 1 < 64) ldg((it + 1) * 16);
        uint32_t aSm = (uint32_t)__cvta_generic_to_shared(&As[buf][0]);
        uint32_t bSm = (uint32_t)__cvta_generic_to_shared(&Bs[buf][0]);
        uint32_t af[2][4], bf[2][4];
        #pragma unroll
        for (int mi = 0; mi < 2; mi++)
            ldsm4(af[mi], aSm + ((wm + mi*16 + aRow)*24 + aK)*2);
        #pragma unroll
        for (int nj = 0; nj < 2; nj++)
            ldsm4(bf[nj], bSm + ((wn + nj*16 + bRow)*24 + bK)*2);
        #pragma unroll
        for (int mi = 0; mi < 2; mi++)
            #pragma unroll
            for (int ni = 0; ni < 4; ni++)
                mma_f16(acc[mi][ni], af[mi], &bf[ni >> 1][(ni & 1) * 2]);
        if (it + 1 < 64) sts(buf ^ 1);
        __syncthreads();
    }

    #pragma unroll
    for (int mi = 0; mi < 2; mi++) {
        int row = m0 + wm + mi * 16 + g;
        #pragma unroll
        for (int ni = 0; ni < 4; ni++) {
            int col = wn + ni * 8 + 2 * q4;
            *(uint32_t*)(Cm + (size_t)row*Eq + col) =
                h2u(acc[mi][ni][0], acc[mi][ni][1]);
            *(uint32_t*)(Cm + (size_t)(row+8)*Eq + col) =
                h2u(acc[mi][ni][2], acc[mi][ni][3]);
        }
    }
}

// ---------------------------------------------------------------------------
extern "C" void kernel_launch(void* const* d_in, const int* in_sizes, int n_in,
                              void* d_out, int out_size)
{
    const float* x     = (const float*)d_in[0];
    const float* pos   = (const float*)d_in[1];
    const float* w_in  = (const float*)d_in[2];
    const float* w_pos = (const float*)d_in[3];
    const float* w_out = (const float*)d_in[4];
    const float* b_out = (const float*)d_in[5];
    const float* ub    = (const float*)d_in[6];
    const float* vbb   = (const float*)d_in[7];
    float* out = (float*)d_out;

    __half *projh, *pkh, *ctxh, *xh, *posh, *winh, *wposh, *wouth;
    float *attn_fb;
    cudaGetSymbolAddress((void**)&projh,   g_projh);
    cudaGetSymbolAddress((void**)&pkh,     g_pkh);
    cudaGetSymbolAddress((void**)&ctxh,    g_ctxh);
    cudaGetSymbolAddress((void**)&xh,      g_xh);
    cudaGetSymbolAddress((void**)&posh,    g_posh);
    cudaGetSymbolAddress((void**)&winh,    g_winh);
    cudaGetSymbolAddress((void**)&wposh,   g_wposh);
    cudaGetSymbolAddress((void**)&wouth,   g_wouth);
    cudaGetSymbolAddress((void**)&attn_fb, g_attn_fb);

    cudaFuncSetAttribute(score_h, cudaFuncAttributeMaxDynamicSharedMemorySize,
                         SCORE_SMEM);

    const size_t OUT_E  = (size_t)BLq * Eq;
    const size_t ATTN_E = (size_t)Bq * Hq * Lq * Lq;
    float* attn = ((size_t)out_size >= OUT_E + ATTN_E) ? (out + OUT_E) : attn_fb;

    // 0) convert inputs to fp16
    f2h_kernel<<<(BLq*Eq/8 + 255)/256, 256>>>(x, xh, BLq*Eq, BLq*Eq);
    f2h_kernel<<<(2048*Eq/8 + 255)/256, 256>>>(pos, posh, Pq*Eq, 2048*Eq);
    f2h_kernel<<<(QKVq*Eq/8 + 255)/256, 256>>>(w_in, winh, QKVq*Eq, QKVq*Eq);
    f2h_kernel<<<(Eq*Eq/8 + 255)/256, 256>>>(w_pos, wposh, Eq*Eq, Eq*Eq);
    f2h_kernel<<<(Eq*Eq/8 + 255)/256, 256>>>(w_out, wouth, Eq*Eq, Eq*Eq);

    // 1) QKV projection (half->half)
    gemm_hh<<<dim3(QKVq/128, BLq/128), 256>>>(xh, winh, projh,
                                              BLq, QKVq, Eq, QKVq);
    // 2) positional keys (padded M=2048)
    gemm_hh<<<dim3(Eq/128, 2048/128), 256>>>(posh, wposh, pkh,
                                             2048, Eq, Eq, Eq);
    // 3) V transpose
    vtrans<<<dim3(Lq/64, Bq*Hq), 128>>>();
    // 4) fused AC + shifted BD logits -> fp16
    score_h<<<dim3(Lq/128, Lq/128, Bq*Hq), 512, SCORE_SMEM>>>(ub, vbb);
    // 5) softmax
    softmax_h<<<Bq*Hq*Lq, 128>>>(attn);
    // 6) ctx = probs @ V -> fp16
    ctx_h<<<dim3(1, Lq/128, Bq*Hq), 256>>>();
    // 7) out projection + bias (half->float)
    gemm_hf<<<dim3(Eq/128, BLq/128), 256>>>(ctxh, wouth, b_out, out,
                                            BLq, Eq, Eq);
}